// round 15
// baseline (speedup 1.0000x reference)
#include <cuda_runtime.h>
#include <cuda_fp16.h>
#include <cstdint>
#include <math.h>

#define C      720
#define HW     9216
#define NPIX   18432
#define IMGW   96
#define NT4    1152              // 2 batch * 24*24 winograd F(4,3) tiles
#define BM     128
#define BN     144
#define CPT    23                // ceil(720/32) k-chunks of 32

// smem stage layout (bytes)
#define SA_H 0
#define SA_L 8192
#define SB_H 16384
#define SB_L 25600
#define STG  34816
#define BAR_OFF (3 * STG)               // 104448: 3x(full,empty) mbarriers
#define SMEM_BYTES (BAR_OFF + 64)       // 104512 -> 2 CTAs/SM

#define NWU (C * C / 2 / 256 + 1)       // 1013 blocks for wU / wt1 halves

// ---------------- scratch -------------------------------------------------------
__device__ float  g_feats[NPIX*C];
__device__ __half g_vh[36*NT4*C], g_vl[36*NT4*C];   // F(4,3) input transform
__device__ float  g_m [36*NT4*C];                   // winograd GEMM output
__device__ __half g_uh[36*C*C], g_ul[36*C*C];       // F(4,3) weights [e][co][ci]
__device__ __half g_yh[NPIX*C], g_yl[NPIX*C];
__device__ __half g_xh[NPIX*C], g_xl[NPIX*C];
__device__ float  g_out[NPIX*C];
__device__ __half g_w1ah[C*C], g_w1al[C*C];
__device__ __half g_w1bh[C*C], g_w1bl[C*C];
__device__ float  g_b3[C], g_b1a[C], g_b1b[C];
__device__ float  g_zero[C];
__device__ float  g_protN[20*C];

// ---------------- helpers -------------------------------------------------------
__device__ __forceinline__ uint32_t smem_u32(const void* p) {
    uint32_t a;
    asm("{ .reg .u64 t; cvta.to.shared.u64 t, %1; cvt.u32.u64 %0, t; }" : "=r"(a) : "l"(p));
    return a;
}

__device__ __forceinline__ void split_h(float v, __half& hi, __half& lo) {
    hi = __float2half_rn(v);
    lo = __float2half_rn(v - __half2float(hi));
}

__device__ __forceinline__ void cp16(uint32_t dst, const void* src, int sz) {
    asm volatile("cp.async.cg.shared.global [%0], [%1], 16, %2;"
                 :: "r"(dst), "l"(src), "r"(sz));
}

__device__ __forceinline__ void ldsm4(uint32_t* r, uint32_t addr) {
    asm volatile("ldmatrix.sync.aligned.m8n8.x4.shared.b16 {%0,%1,%2,%3}, [%4];"
                 : "=r"(r[0]), "=r"(r[1]), "=r"(r[2]), "=r"(r[3]) : "r"(addr));
}

__device__ __forceinline__ void ldsm2(uint32_t& r0, uint32_t& r1, uint32_t addr) {
    asm volatile("ldmatrix.sync.aligned.m8n8.x2.shared.b16 {%0,%1}, [%2];"
                 : "=r"(r0), "=r"(r1) : "r"(addr));
}

__device__ __forceinline__ void mma16816(float* c, const uint32_t* a,
                                         uint32_t b0, uint32_t b1) {
    asm volatile(
        "mma.sync.aligned.m16n8k16.row.col.f32.f16.f16.f32 "
        "{%0,%1,%2,%3}, {%4,%5,%6,%7}, {%8,%9}, {%0,%1,%2,%3};"
        : "+f"(c[0]), "+f"(c[1]), "+f"(c[2]), "+f"(c[3])
        : "r"(a[0]), "r"(a[1]), "r"(a[2]), "r"(a[3]), "r"(b0), "r"(b1));
}

// mbarrier primitives (sm_80/sm_90 baseline)
#define MBAR_INIT(a, cnt) \
    asm volatile("mbarrier.init.shared.b64 [%0], %1;" :: "r"(a), "r"(cnt) : "memory")
#define MBAR_ARRIVE(a) do { \
    uint64_t _st; \
    asm volatile("mbarrier.arrive.shared.b64 %0, [%1];" : "=l"(_st) : "r"(a) : "memory"); \
} while (0)
// .noinc is load-bearing: default variant pre-increments expected count -> deadlock.
#define CP_ASYNC_MBAR_ARRIVE(a) \
    asm volatile("cp.async.mbarrier.arrive.noinc.shared.b64 [%0];" :: "r"(a) : "memory")
#define MBAR_WAIT(a, ph) do { \
    uint32_t _m = (a); uint32_t _p = (uint32_t)(ph); \
    asm volatile("{\n\t.reg .pred P1;\n\t" \
        "WL_%=:\n\t" \
        "mbarrier.try_wait.parity.shared.b64 P1, [%0], %1;\n\t" \
        "@P1 bra.uni WD_%=;\n\t" \
        "bra.uni WL_%=;\n\t" \
        "WD_%=:\n\t}" :: "r"(_m), "r"(_p) : "memory"); \
} while (0)

// B^T row apply (F(4,3)): identical expression order to the scalar version
__device__ __forceinline__ float btrow(int i, float a0, float a1, float a2,
                                       float a3, float a4, float a5) {
    switch (i) {
    case 0:  return 4.f*a0 - 5.f*a2 + a4;
    case 1:  return -4.f*a1 - 4.f*a2 + a3 + a4;
    case 2:  return  4.f*a1 - 4.f*a2 - a3 + a4;
    case 3:  return -2.f*a1 - a2 + 2.f*a3 + a4;
    case 4:  return  2.f*a1 - a2 - 2.f*a3 + a4;
    default: return  4.f*a1 - 5.f*a3 + a5;
    }
}
// A^T row apply (F(4,3) output)
__device__ __forceinline__ float atrow(int i, float a0, float a1, float a2,
                                       float a3, float a4, float a5) {
    switch (i) {
    case 0:  return a0 + a1 + a2 + a3 + a4;
    case 1:  return a1 - a2 + 2.f*a3 - 2.f*a4;
    case 2:  return a1 + a2 + 4.f*a3 + 4.f*a4;
    default: return a1 - a2 + 8.f*a3 - 8.f*a4 + a5;
    }
}

__device__ __forceinline__ uint32_t pack_h2(__half a, __half b) {
    __half2 h = __halves2half2(a, b);
    return *reinterpret_cast<uint32_t*>(&h);
}

// ---------------- fused prep kernel ----------------------------------------------
// blockIdx ranges: [0, NWU) -> wU, [NWU, 2*NWU) -> wt1, then 3 bias, then 20 protos
__global__ void __launch_bounds__(256) prep_all(
    const float* __restrict__ w,   const float* __restrict__ cbg,
    const float* __restrict__ crv,
    const float* __restrict__ w1,  const float* __restrict__ w2,
    const float* __restrict__ pbg, const float* __restrict__ prv,
    const float* __restrict__ cb,  const float* __restrict__ cbb,
    const float* __restrict__ crm,
    const float* __restrict__ pb1, const float* __restrict__ pbb,
    const float* __restrict__ prm, const float* __restrict__ pb2,
    const float* __restrict__ proto)
{
    const int bid = blockIdx.x;

    if (bid < NWU) {
        // ---- F(4,3) weight transform (BN folded), 2 ci per thread ----
        int o2 = bid * 256 + threadIdx.x;
        if (o2 >= C * C / 2) return;
        int o  = o2 * 2;
        int co = o / C;
        int ci = o - co * C;
        float inv = cbg[co] * rsqrtf(crv[co] + 1e-5f);

        float2 g[3][3];
        #pragma unroll
        for (int r = 0; r < 3; ++r)
            #pragma unroll
            for (int c = 0; c < 3; ++c) {
                g[r][c].x = w[((size_t)(co * C + ci)) * 9 + r * 3 + c] * inv;
                g[r][c].y = w[((size_t)(co * C + ci + 1)) * 9 + r * 3 + c] * inv;
            }

        float2 q[6][3];
        #pragma unroll
        for (int c = 0; c < 3; ++c) {
            q[0][c].x = 0.25f * g[0][c].x;                       q[0][c].y = 0.25f * g[0][c].y;
            q[1][c].x = (-1.f/6.f) * (g[0][c].x + g[1][c].x + g[2][c].x);
            q[1][c].y = (-1.f/6.f) * (g[0][c].y + g[1][c].y + g[2][c].y);
            q[2][c].x = (-1.f/6.f) * (g[0][c].x - g[1][c].x + g[2][c].x);
            q[2][c].y = (-1.f/6.f) * (g[0][c].y - g[1][c].y + g[2][c].y);
            q[3][c].x = (1.f/24.f) * g[0][c].x + (1.f/12.f) * g[1][c].x + (1.f/6.f) * g[2][c].x;
            q[3][c].y = (1.f/24.f) * g[0][c].y + (1.f/12.f) * g[1][c].y + (1.f/6.f) * g[2][c].y;
            q[4][c].x = (1.f/24.f) * g[0][c].x - (1.f/12.f) * g[1][c].x + (1.f/6.f) * g[2][c].x;
            q[4][c].y = (1.f/24.f) * g[0][c].y - (1.f/12.f) * g[1][c].y + (1.f/6.f) * g[2][c].y;
            q[5][c] = g[2][c];
        }
        #pragma unroll
        for (int i = 0; i < 6; ++i) {
            float usx[6], usy[6];
            usx[0] = 0.25f * q[i][0].x;                          usy[0] = 0.25f * q[i][0].y;
            usx[1] = (-1.f/6.f) * (q[i][0].x + q[i][1].x + q[i][2].x);
            usy[1] = (-1.f/6.f) * (q[i][0].y + q[i][1].y + q[i][2].y);
            usx[2] = (-1.f/6.f) * (q[i][0].x - q[i][1].x + q[i][2].x);
            usy[2] = (-1.f/6.f) * (q[i][0].y - q[i][1].y + q[i][2].y);
            usx[3] = (1.f/24.f) * q[i][0].x + (1.f/12.f) * q[i][1].x + (1.f/6.f) * q[i][2].x;
            usy[3] = (1.f/24.f) * q[i][0].y + (1.f/12.f) * q[i][1].y + (1.f/6.f) * q[i][2].y;
            usx[4] = (1.f/24.f) * q[i][0].x - (1.f/12.f) * q[i][1].x + (1.f/6.f) * q[i][2].x;
            usy[4] = (1.f/24.f) * q[i][0].y - (1.f/12.f) * q[i][1].y + (1.f/6.f) * q[i][2].y;
            usx[5] = q[i][2].x;                                  usy[5] = q[i][2].y;
            #pragma unroll
            for (int j = 0; j < 6; ++j) {
                int e = i * 6 + j;
                __half hx, lx, hy, ly;
                split_h(usx[j], hx, lx);
                split_h(usy[j], hy, ly);
                size_t idx = (size_t)e * C * C + o;
                *reinterpret_cast<uint32_t*>(&g_uh[idx]) = pack_h2(hx, hy);
                *reinterpret_cast<uint32_t*>(&g_ul[idx]) = pack_h2(lx, ly);
            }
        }
    } else if (bid < 2 * NWU) {
        // ---- 1x1 weight split (BN folded into w1) ----
        int o2 = (bid - NWU) * 256 + threadIdx.x;
        if (o2 >= C * C / 2) return;
        int o  = o2 * 2;
        int co = o / C;
        float inv = pbg[co] * rsqrtf(prv[co] + 1e-5f);
        float2 a = *reinterpret_cast<const float2*>(w1 + o);
        float2 b = *reinterpret_cast<const float2*>(w2 + o);
        __half hx, lx, hy, ly;
        split_h(a.x * inv, hx, lx); split_h(a.y * inv, hy, ly);
        *reinterpret_cast<uint32_t*>(&g_w1ah[o]) = pack_h2(hx, hy);
        *reinterpret_cast<uint32_t*>(&g_w1al[o]) = pack_h2(lx, ly);
        split_h(b.x, hx, lx); split_h(b.y, hy, ly);
        *reinterpret_cast<uint32_t*>(&g_w1bh[o]) = pack_h2(hx, hy);
        *reinterpret_cast<uint32_t*>(&g_w1bl[o]) = pack_h2(lx, ly);
    } else if (bid < 2 * NWU + 3) {
        // ---- biases ----
        int co = (bid - 2 * NWU) * 256 + threadIdx.x;
        if (co >= C) return;
        float inv3 = cbg[co] * rsqrtf(crv[co] + 1e-5f);
        g_b3[co]  = (cb[co]  - crm[co]) * inv3 + cbb[co];
        float inv1 = pbg[co] * rsqrtf(prv[co] + 1e-5f);
        g_b1a[co] = (pb1[co] - prm[co]) * inv1 + pbb[co];
        g_b1b[co] = pb2[co];
    } else {
        // ---- prototype L2 normalization ----
        __shared__ float red[8];
        int p = bid - (2 * NWU + 3);
        const float* src = proto + p * C;
        float ss = 0.f;
        for (int j = threadIdx.x; j < C; j += 256) { float v = src[j]; ss += v * v; }
        #pragma unroll
        for (int o = 16; o; o >>= 1) ss += __shfl_xor_sync(0xffffffffu, ss, o);
        if ((threadIdx.x & 31) == 0) red[threadIdx.x >> 5] = ss;
        __syncthreads();
        if (threadIdx.x == 0) {
            float t = 0.f;
            #pragma unroll
            for (int i = 0; i < 8; ++i) t += red[i];
            red[0] = 1.f / fmaxf(sqrtf(t), 1e-12f);
        }
        __syncthreads();
        float inv = red[0];
        for (int j = threadIdx.x; j < C; j += 256)
            g_protN[p * C + j] = src[j] * inv;
    }
}

// ---------------- build feats: coalesced tiled-transpose --------------------------
__device__ __forceinline__ void ac_coord(int o, int S, int& i0, int& i1, float& w)
{
    float f = (float)o * (float)(S - 1) / 95.f;
    i0 = (int)floorf(f);
    i1 = min(i0 + 1, S - 1);
    w  = f - (float)i0;
}

__global__ void __launch_bounds__(256) build_feats(
    const float* __restrict__ f1, const float* __restrict__ f2,
    const float* __restrict__ f3, const float* __restrict__ f4)
{
    __shared__ float sm[24][33];
    const int tx = threadIdx.x;
    const int ty = threadIdx.y;
    const int p0 = blockIdx.x * 32;
    const int c0 = blockIdx.y * 24;
    const int pix = p0 + tx;
    const int b   = pix / HW;
    const int rem = pix - b * HW;
    const int y   = rem / IMGW;
    const int x   = rem - y * IMGW;

    if (c0 < 48) {
        #pragma unroll
        for (int kk = 0; kk < 3; ++kk) {
            int c = c0 + ty + kk * 8;
            sm[ty + kk * 8][tx] = f1[((size_t)(b * 48 + c) * IMGW + y) * IMGW + x];
        }
    } else if (c0 < 144) {
        int y0, y1, x0, x1; float wy, wx;
        ac_coord(y, 48, y0, y1, wy);
        ac_coord(x, 48, x0, x1, wx);
        #pragma unroll
        for (int kk = 0; kk < 3; ++kk) {
            int c = c0 + ty + kk * 8;
            const float* p = f2 + (size_t)(b * 96 + (c - 48)) * 48 * 48;
            float v00 = p[y0 * 48 + x0], v01 = p[y0 * 48 + x1];
            float v10 = p[y1 * 48 + x0], v11 = p[y1 * 48 + x1];
            sm[ty + kk * 8][tx] = (v00 * (1.f - wy) + v10 * wy) * (1.f - wx)
                                + (v01 * (1.f - wy) + v11 * wy) * wx;
        }
    } else if (c0 < 336) {
        int y0, y1, x0, x1; float wy, wx;
        ac_coord(y, 24, y0, y1, wy);
        ac_coord(x, 24, x0, x1, wx);
        #pragma unroll
        for (int kk = 0; kk < 3; ++kk) {
            int c = c0 + ty + kk * 8;
            const float* p = f3 + (size_t)(b * 192 + (c - 144)) * 24 * 24;
            float v00 = p[y0 * 24 + x0], v01 = p[y0 * 24 + x1];
            float v10 = p[y1 * 24 + x0], v11 = p[y1 * 24 + x1];
            sm[ty + kk * 8][tx] = (v00 * (1.f - wy) + v10 * wy) * (1.f - wx)
                                + (v01 * (1.f - wy) + v11 * wy) * wx;
        }
    } else {
        int y0, y1, x0, x1; float wy, wx;
        ac_coord(y, 12, y0, y1, wy);
        ac_coord(x, 12, x0, x1, wx);
        #pragma unroll
        for (int kk = 0; kk < 3; ++kk) {
            int c = c0 + ty + kk * 8;
            const float* p = f4 + (size_t)(b * 384 + (c - 336)) * 12 * 12;
            float v00 = p[y0 * 12 + x0], v01 = p[y0 * 12 + x1];
            float v10 = p[y1 * 12 + x0], v11 = p[y1 * 12 + x1];
            sm[ty + kk * 8][tx] = (v00 * (1.f - wy) + v10 * wy) * (1.f - wx)
                                + (v01 * (1.f - wy) + v11 * wy) * wx;
        }
    }
    __syncthreads();

    const int tid = ty * 32 + tx;
    #pragma unroll
    for (int i = tid; i < 32 * 24; i += 256) {
        int pp = i / 24;
        int cc = i - pp * 24;
        g_feats[(size_t)(p0 + pp) * C + c0 + cc] = sm[cc][pp];
    }
}

// ---------------- F(4,3) input transform, 2 channels/thread ----------------------
__global__ void __launch_bounds__(384) wino_in(const float* __restrict__ feats)
{
    int tile = blockIdx.x;
    int ci   = threadIdx.x * 2;     // 0..718, blockDim 360
    if (ci >= C) return;
    int b  = tile / 576;
    int r  = tile - b * 576;
    int ty = r / 24, tx = r - ty * 24;
    int y0 = ty * 4 - 1, x0 = tx * 4 - 1;

    float2 d[6][6];
    #pragma unroll
    for (int i = 0; i < 6; ++i) {
        int y = y0 + i;
        #pragma unroll
        for (int j = 0; j < 6; ++j) {
            int x = x0 + j;
            bool ok = (y >= 0) & (y < IMGW) & (x >= 0) & (x < IMGW);
            d[i][j] = ok ? *reinterpret_cast<const float2*>(
                                &feats[(size_t)(b * HW + y * IMGW + x) * C + ci])
                         : make_float2(0.f, 0.f);
        }
    }
    #pragma unroll
    for (int i = 0; i < 6; ++i) {
        float2 t[6];
        #pragma unroll
        for (int c = 0; c < 6; ++c) {
            t[c].x = btrow(i, d[0][c].x, d[1][c].x, d[2][c].x, d[3][c].x, d[4][c].x, d[5][c].x);
            t[c].y = btrow(i, d[0][c].y, d[1][c].y, d[2][c].y, d[3][c].y, d[4][c].y, d[5][c].y);
        }
        #pragma unroll
        for (int j = 0; j < 6; ++j) {
            float vx = btrow(j, t[0].x, t[1].x, t[2].x, t[3].x, t[4].x, t[5].x);
            float vy = btrow(j, t[0].y, t[1].y, t[2].y, t[3].y, t[4].y, t[5].y);
            int e = i * 6 + j;
            __half hx, lx, hy, ly;
            split_h(vx, hx, lx);
            split_h(vy, hy, ly);
            size_t idx = ((size_t)e * NT4 + tile) * C + ci;
            *reinterpret_cast<uint32_t*>(&g_vh[idx]) = pack_h2(hx, hy);
            *reinterpret_cast<uint32_t*>(&g_vl[idx]) = pack_h2(lx, ly);
        }
    }
}

// ---------------- F(4,3) output transform, 2 channels/thread ---------------------
__global__ void __launch_bounds__(384) wino_out(const float* __restrict__ M,
                                                const float* __restrict__ bias)
{
    int tile = blockIdx.x;
    int co   = threadIdx.x * 2;
    if (co >= C) return;
    float2 m[6][6];
    #pragma unroll
    for (int e = 0; e < 36; ++e)
        m[e / 6][e % 6] = *reinterpret_cast<const float2*>(
                               &M[((size_t)e * NT4 + tile) * C + co]);

    float2 bb = *reinterpret_cast<const float2*>(bias + co);
    int b  = tile / 576;
    int r  = tile - b * 576;
    int ty = r / 24, tx = r - ty * 24;
    int py = ty * 4, px = tx * 4;

    #pragma unroll
    for (int i = 0; i < 4; ++i) {
        float2 s[6];
        #pragma unroll
        for (int c = 0; c < 6; ++c) {
            s[c].x = atrow(i, m[0][c].x, m[1][c].x, m[2][c].x, m[3][c].x, m[4][c].x, m[5][c].x);
            s[c].y = atrow(i, m[0][c].y, m[1][c].y, m[2][c].y, m[3][c].y, m[4][c].y, m[5][c].y);
        }
        #pragma unroll
        for (int j = 0; j < 4; ++j) {
            float vx = atrow(j, s[0].x, s[1].x, s[2].x, s[3].x, s[4].x, s[5].x);
            float vy = atrow(j, s[0].y, s[1].y, s[2].y, s[3].y, s[4].y, s[5].y);
            int yy = py + i, xx = px + j;
            float ox = fmaxf(vx + bb.x, 0.f);
            float oy = fmaxf(vy + bb.y, 0.f);
            __half hx, lx, hy, ly;
            split_h(ox, hx, lx);
            split_h(oy, hy, ly);
            size_t idx = (size_t)(b * HW + yy * IMGW + xx) * C + co;
            *reinterpret_cast<uint32_t*>(&g_yh[idx]) = pack_h2(hx, hy);
            *reinterpret_cast<uint32_t*>(&g_yl[idx]) = pack_h2(lx, ly);
        }
    }
}

// ---------------- fp16-split GEMM; compute-first mbarrier pipeline ---------------
__global__ void __launch_bounds__(256, 2) gemm_hmma(
    const __half* __restrict__ Ah, const __half* __restrict__ Al,
    const __half* __restrict__ Bh, const __half* __restrict__ Bl,
    const float* __restrict__ bias,
    __half* __restrict__ Oh, __half* __restrict__ Ol, float* __restrict__ Of,
    int relu_split, size_t zsA, size_t zsB, size_t zsO)
{
    extern __shared__ __align__(128) char smem[];
    const uint32_t sb  = smem_u32(smem);
    const uint32_t bar = sb + BAR_OFF;   // full[s]=bar+s*16, empty[s]=bar+s*16+8
    const int tid = threadIdx.x;
    const int m0  = blockIdx.y * BM;
    const int n0  = blockIdx.x * BN;
    const size_t zA = (size_t)blockIdx.z * zsA;
    const size_t zB = (size_t)blockIdx.z * zsB;
    const size_t zO = (size_t)blockIdx.z * zsO;
    Ah += zA; Al += zA; Bh += zB; Bl += zB;

    if (tid == 0) {
        #pragma unroll
        for (int s = 0; s < 3; ++s) {
            MBAR_INIT(bar + s * 16,     256);
            MBAR_INIT(bar + s * 16 + 8, 256);
        }
    }
    __syncthreads();

    const int arow  = tid >> 1;
    const int ahalf = tid & 1;
    const __half* aptr = (ahalf ? Al : Ah) + (size_t)(m0 + arow) * C;
    const uint32_t a_swz  = (arow >> 1) & 3;
    const uint32_t a_soff = (ahalf ? SA_L : SA_H) + arow * 64;

    auto load_chunk = [&](int c) {
        const uint32_t sdata = sb + (uint32_t)(c % 3) * STG;
        const int ci0 = c * 32;
        #pragma unroll
        for (int c16 = 0; c16 < 4; ++c16) {
            int sz = (ci0 + c16 * 8 < C) ? 16 : 0;
            cp16(sdata + a_soff + (((uint32_t)c16 ^ a_swz) << 4), aptr + ci0 + c16 * 8, sz);
        }
        #pragma unroll
        for (int i = 0; i < 5; ++i) {
            int lin = i * 256 + tid;
            if (lin < 1152) {
                int row = lin >> 3, sub = lin & 7;
                int hb = sub >> 2, c16 = sub & 3;
                int sz = (ci0 + c16 * 8 < C) ? 16 : 0;
                const __half* bp = hb ? Bl : Bh;
                const __half* bsrc = bp + (size_t)(n0 + row) * C + ci0 + c16 * 8;
                uint32_t off = (hb ? SB_L : SB_H) + row * 64
                             + (((uint32_t)(c16 ^ ((row >> 1) & 3))) << 4);
                cp16(sdata + off, bsrc, sz);
            }
        }
        CP_ASYNC_MBAR_ARRIVE(bar + (uint32_t)(c % 3) * 16);
    };

    const int warp = tid >> 5, lane = tid & 31;
    const int wm = warp >> 1, wn = warp & 1;
    const int g  = lane >> 3;
    const int a_rf   = (g & 1) * 8 + (lane & 7);
    const int a_c16b = g >> 1;
    const int b_rf8  = lane & 7;
    const int b_k16  = (lane >> 3) & 1;
    const int b_g2   = (lane >> 4) & 1;
    const int laneB  = lane & 15;
    const int b_rf   = laneB & 7;
    const int b_c16b = laneB >> 3;

    float acc[2][9][4];
    #pragma unroll
    for (int mi = 0; mi < 2; ++mi)
        #pragma unroll
        for (int nj = 0; nj < 9; ++nj)
            #pragma unroll
            for (int q = 0; q < 4; ++q) acc[mi][nj][q] = 0.f;

    load_chunk(0);
    load_chunk(1);
    load_chunk(2);

    for (int c = 0; c < CPT; ++c) {
        MBAR_WAIT(bar + (uint32_t)(c % 3) * 16, (c / 3) & 1);

        const uint32_t sd = sb + (uint32_t)(c % 3) * STG;

        uint32_t aH[2][4], aL[2][4];
        uint32_t bh[2][4], bl[2][4];
        uint32_t rh0, rh1, rl0, rl1;

        auto ldA = [&](int ks) {
            #pragma unroll
            for (int mi = 0; mi < 2; ++mi) {
                int r = wm * 32 + mi * 16 + a_rf;
                uint32_t c16l = (uint32_t)(ks * 2 + a_c16b);
                uint32_t addr = sd + r * 64 + ((c16l ^ ((r >> 1) & 3)) << 4);
                ldsm4(aH[mi], addr + SA_H);
                ldsm4(aL[mi], addr + SA_L);
            }
        };
        auto ldB4 = [&](int ks, int njp, int buf) {
            int r = wn * 72 + (njp * 2 + b_g2) * 8 + b_rf8;
            uint32_t c16l = (uint32_t)(ks * 2 + b_k16);
            uint32_t addr = sd + r * 64 + ((c16l ^ ((r >> 1) & 3)) << 4);
            ldsm4(bh[buf], addr + SB_H);
            ldsm4(bl[buf], addr + SB_L);
        };
        auto ldB2 = [&](int ks) {
            int r = wn * 72 + 8 * 8 + b_rf;
            uint32_t c16l = (uint32_t)(ks * 2 + b_c16b);
            uint32_t addr = sd + r * 64 + ((c16l ^ ((r >> 1) & 3)) << 4);
            ldsm2(rh0, rh1, addr + SB_H);
            ldsm2(rl0, rl1, addr + SB_L);
        };
        auto mm12 = [&](int njp, int buf) {
            const int j0 = njp * 2, j1 = njp * 2 + 1;
            uint32_t* h = bh[buf];
            uint32_t* l = bl[buf];
            mma16816(acc[0][j0], aH[0], h[0], h[1]);
            mma16816(acc[1][j0], aH[1], h[0], h[1]);
            mma16816(acc[0][j1], aH[0], h[2], h[3]);
            mma16816(acc[1][j1], aH[1], h[2], h[3]);
            mma16816(acc[0][j0], aH[0], l[0], l[1]);
            mma16816(acc[1][j0], aH[1], l[0], l[1]);
            mma16816(acc[0][j1], aH[0], l[2], l[3]);
            mma16816(acc[1][j1], aH[1], l[2], l[3]);
            mma16816(acc[0][j0], aL[0], h[0], h[1]);
            mma16816(acc[1][j0], aL[1], h[0], h[1]);
            mma16816(acc[0][j1], aL[0], h[2], h[3]);
            mma16816(acc[1][j1], aL[1], h[2], h[3]);
        };
        auto mm6 = [&]() {
            mma16816(acc[0][8], aH[0], rh0, rh1);
            mma16816(acc[1][8], aH[1], rh0, rh1);
            mma16816(acc[0][8], aH[0], rl0, rl1);
            mma16816(acc[1][8], aH[1], rl0, rl1);
            mma16816(acc[0][8], aL[0], rh0, rh1);
            mma16816(acc[1][8], aL[1], rh0, rh1);
        };

        // ---- ks = 0 ----
        ldA(0);
        ldB4(0, 0, 0);
        #pragma unroll
        for (int njp = 0; njp < 4; ++njp) {
            const int cur = njp & 1, nxt = cur ^ 1;
            if (njp < 3) {
                ldB4(0, njp + 1, nxt);
            } else {
                ldB2(0);
                ldB4(1, 0, nxt);
            }
            mm12(njp, cur);
        }
        mm6();
        // ---- ks = 1 ----
        ldA(1);
        #pragma unroll
        for (int njp = 0; njp < 4; ++njp) {
            const int cur = njp & 1, nxt = cur ^ 1;
            if (njp < 3) ldB4(1, njp + 1, nxt);
            else         ldB2(1);
            mm12(njp, cur);
        }
        mm6();

        MBAR_ARRIVE(bar + (uint32_t)(c % 3) * 16 + 8);

        const int nc = c + 3;
        if (nc < CPT) {
            MBAR_WAIT(bar + (uint32_t)(nc % 3) * 16 + 8, ((nc / 3) - 1) & 1);
            load_chunk(nc);
        }
    }

    // epilogue
    const int qrow = lane >> 2;
    const int qcol = (lane & 3) * 2;
    #pragma unroll
    for (int nj = 0; nj < 9; ++nj) {
        const int ncol = n0 + wn * 72 + nj * 8 + qcol;
        const float b0 = __ldg(bias + ncol);
        const float b1 = __ldg(bias + ncol + 1);
        #pragma unroll
        for (int mi = 0; mi < 2; ++mi) {
            const int mr = m0 + wm * 32 + mi * 16 + qrow;
            float v00 = acc[mi][nj][0] + b0;
            float v01 = acc[mi][nj][1] + b1;
            float v10 = acc[mi][nj][2] + b0;
            float v11 = acc[mi][nj][3] + b1;
            if (relu_split) {
                v00 = fmaxf(v00, 0.f); v01 = fmaxf(v01, 0.f);
                v10 = fmaxf(v10, 0.f); v11 = fmaxf(v11, 0.f);
                __half h0, l0, h1, l1;
                split_h(v00, h0, l0); split_h(v01, h1, l1);
                *reinterpret_cast<__half2*>(Oh + (size_t)mr * C + ncol) = __halves2half2(h0, h1);
                *reinterpret_cast<__half2*>(Ol + (size_t)mr * C + ncol) = __halves2half2(l0, l1);
                split_h(v10, h0, l0); split_h(v11, h1, l1);
                *reinterpret_cast<__half2*>(Oh + (size_t)(mr + 8) * C + ncol) = __halves2half2(h0, h1);
                *reinterpret_cast<__half2*>(Ol + (size_t)(mr + 8) * C + ncol) = __halves2half2(l0, l1);
            } else {
                float* ofp = Of + zO;
                *reinterpret_cast<float2*>(ofp + (size_t)mr * C + ncol)       = make_float2(v00, v01);
                *reinterpret_cast<float2*>(ofp + (size_t)(mr + 8) * C + ncol) = make_float2(v10, v11);
            }
        }
    }
}

// ---------------- finalize --------------------------------------------------------
__global__ __launch_bounds__(256) void finalize(
    const float* __restrict__ p,
    const float* __restrict__ lng, const float* __restrict__ lnb,
    const float* __restrict__ lmg, const float* __restrict__ lmb,
    float* __restrict__ out)
{
    int gw   = (blockIdx.x * 256 + threadIdx.x) >> 5;
    int lane = threadIdx.x & 31;
    if (gw >= NPIX) return;
    const float* row = p + (size_t)gw * C;

    float x[23];
    float s = 0.f, ss = 0.f;
    #pragma unroll
    for (int i = 0; i < 23; ++i) {
        int j = lane + i * 32;
        float v = (j < C) ? row[j] : 0.f;
        x[i] = v; s += v; ss += v * v;
    }
    #pragma unroll
    for (int o = 16; o; o >>= 1) {
        s  += __shfl_xor_sync(0xffffffffu, s,  o);
        ss += __shfl_xor_sync(0xffffffffu, ss, o);
    }
    float mu   = s * (1.f / C);
    float var  = ss * (1.f / C) - mu * mu;
    float rstd = rsqrtf(var + 1e-5f);

    float nsq = 0.f;
    #pragma unroll
    for (int i = 0; i < 23; ++i) {
        int j = lane + i * 32;
        float v = 0.f;
        if (j < C) v = (x[i] - mu) * rstd * lng[j] + lnb[j];
        x[i] = v;
        nsq += v * v;
    }
    #pragma unroll
    for (int o = 16; o; o >>= 1) nsq += __shfl_xor_sync(0xffffffffu, nsq, o);
    float inv = 1.f / fmaxf(sqrtf(nsq), 1e-12f);

    float sc[2];
    #pragma unroll
    for (int k = 0; k < 2; ++k) {
        float best = -3.4e38f;
        for (int m = 0; m < 10; ++m) {
            const float* pr = g_protN + (k * 10 + m) * C;
            float d = 0.f;
            #pragma unroll
            for (int i = 0; i < 23; ++i) {
                int j = lane + i * 32;
                if (j < C) d += x[i] * pr[j];
            }
            #pragma unroll
            for (int o = 16; o; o >>= 1) d += __shfl_xor_sync(0xffffffffu, d, o);
            best = fmaxf(best, d * inv);
        }
        sc[k] = best;
    }

    float mu2 = 0.5f * (sc[0] + sc[1]);
    float d0 = sc[0] - mu2, d1 = sc[1] - mu2;
    float va = 0.5f * (d0 * d0 + d1 * d1);
    float r2 = rsqrtf(va + 1e-5f);
    if (lane < 2) {
        int b = gw / HW, rem = gw - b * HW;
        out[(b * 2 + lane) * HW + rem] = (sc[lane] - mu2) * r2 * lmg[lane] + lmb[lane];
    }
}

// ---------------- launch ----------------------------------------------------------
extern "C" void kernel_launch(void* const* d_in, const int* in_sizes, int n_in,
                              void* d_out, int out_size)
{
    const float* feat1      = (const float*)d_in[0];
    const float* feat2      = (const float*)d_in[1];
    const float* feat3      = (const float*)d_in[2];
    const float* feat4      = (const float*)d_in[3];
    const float* cls_w      = (const float*)d_in[4];
    const float* cls_b      = (const float*)d_in[5];
    const float* cls_bn_g   = (const float*)d_in[6];
    const float* cls_bn_b   = (const float*)d_in[7];
    const float* cls_bn_rm  = (const float*)d_in[8];
    const float* cls_bn_rv  = (const float*)d_in[9];
    const float* proj_w1    = (const float*)d_in[10];
    const float* proj_b1    = (const float*)d_in[11];
    const float* proj_bn_g  = (const float*)d_in[12];
    const float* proj_bn_b  = (const float*)d_in[13];
    const float* proj_bn_rm = (const float*)d_in[14];
    const float* proj_bn_rv = (const float*)d_in[15];
    const float* proj_w2    = (const float*)d_in[16];
    const float* proj_b2    = (const float*)d_in[17];
    const float* ln_feat_g  = (const float*)d_in[18];
    const float* ln_feat_b  = (const float*)d_in[19];
    const float* ln_mask_g  = (const float*)d_in[20];
    const float* ln_mask_b  = (const float*)d_in[21];
    const float* prototypes = (const float*)d_in[22];
    float* out = (float*)d_out;

    float *feats, *gm, *gout, *b3, *b1a, *b1b, *bz;
    __half *vh, *vl, *uh, *ul, *yh, *yl, *xh, *xl, *w1ah, *w1al, *w1bh, *w1bl;
    cudaGetSymbolAddress((void**)&feats, g_feats);
    cudaGetSymbolAddress((void**)&vh,    g_vh);
    cudaGetSymbolAddress((void**)&vl,    g_vl);
    cudaGetSymbolAddress((void**)&gm,    g_m);
    cudaGetSymbolAddress((void**)&uh,    g_uh);
    cudaGetSymbolAddress((void**)&ul,    g_ul);
    cudaGetSymbolAddress((void**)&yh,    g_yh);
    cudaGetSymbolAddress((void**)&yl,    g_yl);
    cudaGetSymbolAddress((void**)&xh,    g_xh);
    cudaGetSymbolAddress((void**)&xl,    g_xl);
    cudaGetSymbolAddress((void**)&gout,  g_out);
    cudaGetSymbolAddress((void**)&w1ah,  g_w1ah);
    cudaGetSymbolAddress((void**)&w1al,  g_w1al);
    cudaGetSymbolAddress((void**)&w1bh,  g_w1bh);
    cudaGetSymbolAddress((void**)&w1bl,  g_w1bl);
    cudaGetSymbolAddress((void**)&b3,    g_b3);
    cudaGetSymbolAddress((void**)&b1a,   g_b1a);
    cudaGetSymbolAddress((void**)&b1b,   g_b1b);
    cudaGetSymbolAddress((void**)&bz,    g_zero);

    cudaFuncSetAttribute(gemm_hmma, cudaFuncAttributeMaxDynamicSharedMemorySize, SMEM_BYTES);

    // Fused preps: one launch covers wU + wt1 + bias + protos (independent work).
    prep_all<<<2 * NWU + 3 + 20, 256>>>(cls_w, cls_bn_g, cls_bn_rv,
                                        proj_w1, proj_w2, proj_bn_g, proj_bn_rv,
                                        cls_b, cls_bn_b, cls_bn_rm,
                                        proj_b1, proj_bn_b, proj_bn_rm, proj_b2,
                                        prototypes);                               // 0
    {
        dim3 bfGrid(NPIX / 32, 30);
        dim3 bfBlock(32, 8);
        build_feats<<<bfGrid, bfBlock>>>(feat1, feat2, feat3, feat4);              // 1
    }
    wino_in<<<NT4, 360>>>(feats);                                                  // 2

    // 36 winograd GEMMs: [1152,720] x [720,720] -> fp32 M
    dim3 gridW(C / BN, NT4 / BM, 36);                                              // 3
    gemm_hmma<<<gridW, 256, SMEM_BYTES>>>(vh, vl, uh, ul, bz,
                                          nullptr, nullptr, gm, 0,
                                          (size_t)NT4 * C, (size_t)C * C,
                                          (size_t)NT4 * C);

    wino_out<<<NT4, 360>>>(gm, b3);                                                // 4

    dim3 grid1(C / BN, NPIX / BM, 1);
    gemm_hmma<<<grid1, 256, SMEM_BYTES>>>(yh, yl, w1ah, w1al, b1a,
                                          xh, xl, nullptr, 1, 0, 0, 0);            // 5
    gemm_hmma<<<grid1, 256, SMEM_BYTES>>>(xh, xl, w1bh, w1bl, b1b,
                                          nullptr, nullptr, gout, 0, 0, 0, 0);     // 6

    finalize<<<(NPIX * 32 + 255) / 256, 256>>>(gout, ln_feat_g, ln_feat_b,
                                               ln_mask_g, ln_mask_b, out);         // 7
}

// round 16
// speedup vs baseline: 1.0081x; 1.0081x over previous
#include <cuda_runtime.h>
#include <cuda_fp16.h>
#include <cstdint>
#include <math.h>

#define C      720
#define HW     9216
#define NPIX   18432
#define IMGW   96
#define NT4    1152              // 2 batch * 24*24 winograd F(4,3) tiles
#define BM     128
#define BN     144
#define CPT    23                // ceil(720/32) k-chunks of 32

// smem stage layout (bytes)
#define SA_H 0
#define SA_L 8192
#define SB_H 16384
#define SB_L 25600
#define STG  34816
#define BAR_OFF (3 * STG)               // 104448: 3x(full,empty) mbarriers
#define SMEM_BYTES (BAR_OFF + 64)       // 104512 -> 2 CTAs/SM

#define NWU (C * C / 2 / 256 + 1)       // 1013 blocks for wU / wt1 halves
#define PROT_SMEM (20 * C * 4)          // 57600 bytes

// ---------------- scratch -------------------------------------------------------
__device__ float  g_feats[NPIX*C];
__device__ __half g_vh[36*NT4*C], g_vl[36*NT4*C];   // F(4,3) input transform
__device__ float  g_m [36*NT4*C];                   // winograd GEMM output
__device__ __half g_uh[36*C*C], g_ul[36*C*C];       // F(4,3) weights [e][co][ci]
__device__ __half g_yh[NPIX*C], g_yl[NPIX*C];
__device__ __half g_xh[NPIX*C], g_xl[NPIX*C];
__device__ float  g_out[NPIX*C];
__device__ __half g_w1ah[C*C], g_w1al[C*C];
__device__ __half g_w1bh[C*C], g_w1bl[C*C];
__device__ float  g_b3[C], g_b1a[C], g_b1b[C];
__device__ float  g_zero[C];
__device__ float  g_protN[20*C];

// ---------------- helpers -------------------------------------------------------
__device__ __forceinline__ uint32_t smem_u32(const void* p) {
    uint32_t a;
    asm("{ .reg .u64 t; cvta.to.shared.u64 t, %1; cvt.u32.u64 %0, t; }" : "=r"(a) : "l"(p));
    return a;
}

__device__ __forceinline__ void split_h(float v, __half& hi, __half& lo) {
    hi = __float2half_rn(v);
    lo = __float2half_rn(v - __half2float(hi));
}

__device__ __forceinline__ void cp16(uint32_t dst, const void* src, int sz) {
    asm volatile("cp.async.cg.shared.global [%0], [%1], 16, %2;"
                 :: "r"(dst), "l"(src), "r"(sz));
}

__device__ __forceinline__ void ldsm4(uint32_t* r, uint32_t addr) {
    asm volatile("ldmatrix.sync.aligned.m8n8.x4.shared.b16 {%0,%1,%2,%3}, [%4];"
                 : "=r"(r[0]), "=r"(r[1]), "=r"(r[2]), "=r"(r[3]) : "r"(addr));
}

__device__ __forceinline__ void ldsm2(uint32_t& r0, uint32_t& r1, uint32_t addr) {
    asm volatile("ldmatrix.sync.aligned.m8n8.x2.shared.b16 {%0,%1}, [%2];"
                 : "=r"(r0), "=r"(r1) : "r"(addr));
}

__device__ __forceinline__ void mma16816(float* c, const uint32_t* a,
                                         uint32_t b0, uint32_t b1) {
    asm volatile(
        "mma.sync.aligned.m16n8k16.row.col.f32.f16.f16.f32 "
        "{%0,%1,%2,%3}, {%4,%5,%6,%7}, {%8,%9}, {%0,%1,%2,%3};"
        : "+f"(c[0]), "+f"(c[1]), "+f"(c[2]), "+f"(c[3])
        : "r"(a[0]), "r"(a[1]), "r"(a[2]), "r"(a[3]), "r"(b0), "r"(b1));
}

// mbarrier primitives (sm_80/sm_90 baseline)
#define MBAR_INIT(a, cnt) \
    asm volatile("mbarrier.init.shared.b64 [%0], %1;" :: "r"(a), "r"(cnt) : "memory")
#define MBAR_ARRIVE(a) do { \
    uint64_t _st; \
    asm volatile("mbarrier.arrive.shared.b64 %0, [%1];" : "=l"(_st) : "r"(a) : "memory"); \
} while (0)
// .noinc is load-bearing: default variant pre-increments expected count -> deadlock.
#define CP_ASYNC_MBAR_ARRIVE(a) \
    asm volatile("cp.async.mbarrier.arrive.noinc.shared.b64 [%0];" :: "r"(a) : "memory")
#define MBAR_WAIT(a, ph) do { \
    uint32_t _m = (a); uint32_t _p = (uint32_t)(ph); \
    asm volatile("{\n\t.reg .pred P1;\n\t" \
        "WL_%=:\n\t" \
        "mbarrier.try_wait.parity.shared.b64 P1, [%0], %1;\n\t" \
        "@P1 bra.uni WD_%=;\n\t" \
        "bra.uni WL_%=;\n\t" \
        "WD_%=:\n\t}" :: "r"(_m), "r"(_p) : "memory"); \
} while (0)

// B^T row apply (F(4,3)): identical expression order to the scalar version
__device__ __forceinline__ float btrow(int i, float a0, float a1, float a2,
                                       float a3, float a4, float a5) {
    switch (i) {
    case 0:  return 4.f*a0 - 5.f*a2 + a4;
    case 1:  return -4.f*a1 - 4.f*a2 + a3 + a4;
    case 2:  return  4.f*a1 - 4.f*a2 - a3 + a4;
    case 3:  return -2.f*a1 - a2 + 2.f*a3 + a4;
    case 4:  return  2.f*a1 - a2 - 2.f*a3 + a4;
    default: return  4.f*a1 - 5.f*a3 + a5;
    }
}
// A^T row apply (F(4,3) output)
__device__ __forceinline__ float atrow(int i, float a0, float a1, float a2,
                                       float a3, float a4, float a5) {
    switch (i) {
    case 0:  return a0 + a1 + a2 + a3 + a4;
    case 1:  return a1 - a2 + 2.f*a3 - 2.f*a4;
    case 2:  return a1 + a2 + 4.f*a3 + 4.f*a4;
    default: return a1 - a2 + 8.f*a3 - 8.f*a4 + a5;
    }
}

__device__ __forceinline__ uint32_t pack_h2(__half a, __half b) {
    __half2 h = __halves2half2(a, b);
    return *reinterpret_cast<uint32_t*>(&h);
}

// ---------------- fused prep kernel ----------------------------------------------
__global__ void __launch_bounds__(256) prep_all(
    const float* __restrict__ w,   const float* __restrict__ cbg,
    const float* __restrict__ crv,
    const float* __restrict__ w1,  const float* __restrict__ w2,
    const float* __restrict__ pbg, const float* __restrict__ prv,
    const float* __restrict__ cb,  const float* __restrict__ cbb,
    const float* __restrict__ crm,
    const float* __restrict__ pb1, const float* __restrict__ pbb,
    const float* __restrict__ prm, const float* __restrict__ pb2,
    const float* __restrict__ proto)
{
    const int bid = blockIdx.x;

    if (bid < NWU) {
        int o2 = bid * 256 + threadIdx.x;
        if (o2 >= C * C / 2) return;
        int o  = o2 * 2;
        int co = o / C;
        int ci = o - co * C;
        float inv = cbg[co] * rsqrtf(crv[co] + 1e-5f);

        float2 g[3][3];
        #pragma unroll
        for (int r = 0; r < 3; ++r)
            #pragma unroll
            for (int c = 0; c < 3; ++c) {
                g[r][c].x = w[((size_t)(co * C + ci)) * 9 + r * 3 + c] * inv;
                g[r][c].y = w[((size_t)(co * C + ci + 1)) * 9 + r * 3 + c] * inv;
            }

        float2 q[6][3];
        #pragma unroll
        for (int c = 0; c < 3; ++c) {
            q[0][c].x = 0.25f * g[0][c].x;                       q[0][c].y = 0.25f * g[0][c].y;
            q[1][c].x = (-1.f/6.f) * (g[0][c].x + g[1][c].x + g[2][c].x);
            q[1][c].y = (-1.f/6.f) * (g[0][c].y + g[1][c].y + g[2][c].y);
            q[2][c].x = (-1.f/6.f) * (g[0][c].x - g[1][c].x + g[2][c].x);
            q[2][c].y = (-1.f/6.f) * (g[0][c].y - g[1][c].y + g[2][c].y);
            q[3][c].x = (1.f/24.f) * g[0][c].x + (1.f/12.f) * g[1][c].x + (1.f/6.f) * g[2][c].x;
            q[3][c].y = (1.f/24.f) * g[0][c].y + (1.f/12.f) * g[1][c].y + (1.f/6.f) * g[2][c].y;
            q[4][c].x = (1.f/24.f) * g[0][c].x - (1.f/12.f) * g[1][c].x + (1.f/6.f) * g[2][c].x;
            q[4][c].y = (1.f/24.f) * g[0][c].y - (1.f/12.f) * g[1][c].y + (1.f/6.f) * g[2][c].y;
            q[5][c] = g[2][c];
        }
        #pragma unroll
        for (int i = 0; i < 6; ++i) {
            float usx[6], usy[6];
            usx[0] = 0.25f * q[i][0].x;                          usy[0] = 0.25f * q[i][0].y;
            usx[1] = (-1.f/6.f) * (q[i][0].x + q[i][1].x + q[i][2].x);
            usy[1] = (-1.f/6.f) * (q[i][0].y + q[i][1].y + q[i][2].y);
            usx[2] = (-1.f/6.f) * (q[i][0].x - q[i][1].x + q[i][2].x);
            usy[2] = (-1.f/6.f) * (q[i][0].y - q[i][1].y + q[i][2].y);
            usx[3] = (1.f/24.f) * q[i][0].x + (1.f/12.f) * q[i][1].x + (1.f/6.f) * q[i][2].x;
            usy[3] = (1.f/24.f) * q[i][0].y + (1.f/12.f) * q[i][1].y + (1.f/6.f) * q[i][2].y;
            usx[4] = (1.f/24.f) * q[i][0].x - (1.f/12.f) * q[i][1].x + (1.f/6.f) * q[i][2].x;
            usy[4] = (1.f/24.f) * q[i][0].y - (1.f/12.f) * q[i][1].y + (1.f/6.f) * q[i][2].y;
            usx[5] = q[i][2].x;                                  usy[5] = q[i][2].y;
            #pragma unroll
            for (int j = 0; j < 6; ++j) {
                int e = i * 6 + j;
                __half hx, lx, hy, ly;
                split_h(usx[j], hx, lx);
                split_h(usy[j], hy, ly);
                size_t idx = (size_t)e * C * C + o;
                *reinterpret_cast<uint32_t*>(&g_uh[idx]) = pack_h2(hx, hy);
                *reinterpret_cast<uint32_t*>(&g_ul[idx]) = pack_h2(lx, ly);
            }
        }
    } else if (bid < 2 * NWU) {
        int o2 = (bid - NWU) * 256 + threadIdx.x;
        if (o2 >= C * C / 2) return;
        int o  = o2 * 2;
        int co = o / C;
        float inv = pbg[co] * rsqrtf(prv[co] + 1e-5f);
        float2 a = *reinterpret_cast<const float2*>(w1 + o);
        float2 b = *reinterpret_cast<const float2*>(w2 + o);
        __half hx, lx, hy, ly;
        split_h(a.x * inv, hx, lx); split_h(a.y * inv, hy, ly);
        *reinterpret_cast<uint32_t*>(&g_w1ah[o]) = pack_h2(hx, hy);
        *reinterpret_cast<uint32_t*>(&g_w1al[o]) = pack_h2(lx, ly);
        split_h(b.x, hx, lx); split_h(b.y, hy, ly);
        *reinterpret_cast<uint32_t*>(&g_w1bh[o]) = pack_h2(hx, hy);
        *reinterpret_cast<uint32_t*>(&g_w1bl[o]) = pack_h2(lx, ly);
    } else if (bid < 2 * NWU + 3) {
        int co = (bid - 2 * NWU) * 256 + threadIdx.x;
        if (co >= C) return;
        float inv3 = cbg[co] * rsqrtf(crv[co] + 1e-5f);
        g_b3[co]  = (cb[co]  - crm[co]) * inv3 + cbb[co];
        float inv1 = pbg[co] * rsqrtf(prv[co] + 1e-5f);
        g_b1a[co] = (pb1[co] - prm[co]) * inv1 + pbb[co];
        g_b1b[co] = pb2[co];
    } else {
        __shared__ float red[8];
        int p = bid - (2 * NWU + 3);
        const float* src = proto + p * C;
        float ss = 0.f;
        for (int j = threadIdx.x; j < C; j += 256) { float v = src[j]; ss += v * v; }
        #pragma unroll
        for (int o = 16; o; o >>= 1) ss += __shfl_xor_sync(0xffffffffu, ss, o);
        if ((threadIdx.x & 31) == 0) red[threadIdx.x >> 5] = ss;
        __syncthreads();
        if (threadIdx.x == 0) {
            float t = 0.f;
            #pragma unroll
            for (int i = 0; i < 8; ++i) t += red[i];
            red[0] = 1.f / fmaxf(sqrtf(t), 1e-12f);
        }
        __syncthreads();
        float inv = red[0];
        for (int j = threadIdx.x; j < C; j += 256)
            g_protN[p * C + j] = src[j] * inv;
    }
}

// ---------------- build feats: coalesced tiled-transpose --------------------------
__device__ __forceinline__ void ac_coord(int o, int S, int& i0, int& i1, float& w)
{
    float f = (float)o * (float)(S - 1) / 95.f;
    i0 = (int)floorf(f);
    i1 = min(i0 + 1, S - 1);
    w  = f - (float)i0;
}

__global__ void __launch_bounds__(256) build_feats(
    const float* __restrict__ f1, const float* __restrict__ f2,
    const float* __restrict__ f3, const float* __restrict__ f4)
{
    __shared__ float sm[24][33];
    const int tx = threadIdx.x;
    const int ty = threadIdx.y;
    const int p0 = blockIdx.x * 32;
    const int c0 = blockIdx.y * 24;
    const int pix = p0 + tx;
    const int b   = pix / HW;
    const int rem = pix - b * HW;
    const int y   = rem / IMGW;
    const int x   = rem - y * IMGW;

    if (c0 < 48) {
        #pragma unroll
        for (int kk = 0; kk < 3; ++kk) {
            int c = c0 + ty + kk * 8;
            sm[ty + kk * 8][tx] = f1[((size_t)(b * 48 + c) * IMGW + y) * IMGW + x];
        }
    } else if (c0 < 144) {
        int y0, y1, x0, x1; float wy, wx;
        ac_coord(y, 48, y0, y1, wy);
        ac_coord(x, 48, x0, x1, wx);
        #pragma unroll
        for (int kk = 0; kk < 3; ++kk) {
            int c = c0 + ty + kk * 8;
            const float* p = f2 + (size_t)(b * 96 + (c - 48)) * 48 * 48;
            float v00 = p[y0 * 48 + x0], v01 = p[y0 * 48 + x1];
            float v10 = p[y1 * 48 + x0], v11 = p[y1 * 48 + x1];
            sm[ty + kk * 8][tx] = (v00 * (1.f - wy) + v10 * wy) * (1.f - wx)
                                + (v01 * (1.f - wy) + v11 * wy) * wx;
        }
    } else if (c0 < 336) {
        int y0, y1, x0, x1; float wy, wx;
        ac_coord(y, 24, y0, y1, wy);
        ac_coord(x, 24, x0, x1, wx);
        #pragma unroll
        for (int kk = 0; kk < 3; ++kk) {
            int c = c0 + ty + kk * 8;
            const float* p = f3 + (size_t)(b * 192 + (c - 144)) * 24 * 24;
            float v00 = p[y0 * 24 + x0], v01 = p[y0 * 24 + x1];
            float v10 = p[y1 * 24 + x0], v11 = p[y1 * 24 + x1];
            sm[ty + kk * 8][tx] = (v00 * (1.f - wy) + v10 * wy) * (1.f - wx)
                                + (v01 * (1.f - wy) + v11 * wy) * wx;
        }
    } else {
        int y0, y1, x0, x1; float wy, wx;
        ac_coord(y, 12, y0, y1, wy);
        ac_coord(x, 12, x0, x1, wx);
        #pragma unroll
        for (int kk = 0; kk < 3; ++kk) {
            int c = c0 + ty + kk * 8;
            const float* p = f4 + (size_t)(b * 384 + (c - 336)) * 12 * 12;
            float v00 = p[y0 * 12 + x0], v01 = p[y0 * 12 + x1];
            float v10 = p[y1 * 12 + x0], v11 = p[y1 * 12 + x1];
            sm[ty + kk * 8][tx] = (v00 * (1.f - wy) + v10 * wy) * (1.f - wx)
                                + (v01 * (1.f - wy) + v11 * wy) * wx;
        }
    }
    __syncthreads();

    const int tid = ty * 32 + tx;
    #pragma unroll
    for (int i = tid; i < 32 * 24; i += 256) {
        int pp = i / 24;
        int cc = i - pp * 24;
        g_feats[(size_t)(p0 + pp) * C + c0 + cc] = sm[cc][pp];
    }
}

// ---------------- F(4,3) input transform, 2 channels/thread ----------------------
__global__ void __launch_bounds__(384) wino_in(const float* __restrict__ feats)
{
    int tile = blockIdx.x;
    int ci   = threadIdx.x * 2;     // 0..718, blockDim 360
    if (ci >= C) return;
    int b  = tile / 576;
    int r  = tile - b * 576;
    int ty = r / 24, tx = r - ty * 24;
    int y0 = ty * 4 - 1, x0 = tx * 4 - 1;

    float2 d[6][6];
    #pragma unroll
    for (int i = 0; i < 6; ++i) {
        int y = y0 + i;
        #pragma unroll
        for (int j = 0; j < 6; ++j) {
            int x = x0 + j;
            bool ok = (y >= 0) & (y < IMGW) & (x >= 0) & (x < IMGW);
            d[i][j] = ok ? *reinterpret_cast<const float2*>(
                                &feats[(size_t)(b * HW + y * IMGW + x) * C + ci])
                         : make_float2(0.f, 0.f);
        }
    }
    #pragma unroll
    for (int i = 0; i < 6; ++i) {
        float2 t[6];
        #pragma unroll
        for (int c = 0; c < 6; ++c) {
            t[c].x = btrow(i, d[0][c].x, d[1][c].x, d[2][c].x, d[3][c].x, d[4][c].x, d[5][c].x);
            t[c].y = btrow(i, d[0][c].y, d[1][c].y, d[2][c].y, d[3][c].y, d[4][c].y, d[5][c].y);
        }
        #pragma unroll
        for (int j = 0; j < 6; ++j) {
            float vx = btrow(j, t[0].x, t[1].x, t[2].x, t[3].x, t[4].x, t[5].x);
            float vy = btrow(j, t[0].y, t[1].y, t[2].y, t[3].y, t[4].y, t[5].y);
            int e = i * 6 + j;
            __half hx, lx, hy, ly;
            split_h(vx, hx, lx);
            split_h(vy, hy, ly);
            size_t idx = ((size_t)e * NT4 + tile) * C + ci;
            *reinterpret_cast<uint32_t*>(&g_vh[idx]) = pack_h2(hx, hy);
            *reinterpret_cast<uint32_t*>(&g_vl[idx]) = pack_h2(lx, ly);
        }
    }
}

// ---------------- F(4,3) output transform, 4 channels/thread ---------------------
__global__ void __launch_bounds__(192) wino_out(const float* __restrict__ M,
                                                const float* __restrict__ bias)
{
    int tile = blockIdx.x;
    int co   = threadIdx.x * 4;     // 0..716, blockDim 180 used of 192
    if (co >= C) return;
    float4 m[6][6];
    #pragma unroll
    for (int e = 0; e < 36; ++e)
        m[e / 6][e % 6] = *reinterpret_cast<const float4*>(
                               &M[((size_t)e * NT4 + tile) * C + co]);

    float4 bb = *reinterpret_cast<const float4*>(bias + co);
    int b  = tile / 576;
    int r  = tile - b * 576;
    int ty = r / 24, tx = r - ty * 24;
    int py = ty * 4, px = tx * 4;

    #pragma unroll
    for (int i = 0; i < 4; ++i) {
        float4 s[6];
        #pragma unroll
        for (int c = 0; c < 6; ++c) {
            s[c].x = atrow(i, m[0][c].x, m[1][c].x, m[2][c].x, m[3][c].x, m[4][c].x, m[5][c].x);
            s[c].y = atrow(i, m[0][c].y, m[1][c].y, m[2][c].y, m[3][c].y, m[4][c].y, m[5][c].y);
            s[c].z = atrow(i, m[0][c].z, m[1][c].z, m[2][c].z, m[3][c].z, m[4][c].z, m[5][c].z);
            s[c].w = atrow(i, m[0][c].w, m[1][c].w, m[2][c].w, m[3][c].w, m[4][c].w, m[5][c].w);
        }
        #pragma unroll
        for (int j = 0; j < 4; ++j) {
            float vx = atrow(j, s[0].x, s[1].x, s[2].x, s[3].x, s[4].x, s[5].x);
            float vy = atrow(j, s[0].y, s[1].y, s[2].y, s[3].y, s[4].y, s[5].y);
            float vz = atrow(j, s[0].z, s[1].z, s[2].z, s[3].z, s[4].z, s[5].z);
            float vw = atrow(j, s[0].w, s[1].w, s[2].w, s[3].w, s[4].w, s[5].w);
            int yy = py + i, xx = px + j;
            float ox = fmaxf(vx + bb.x, 0.f);
            float oy = fmaxf(vy + bb.y, 0.f);
            float oz = fmaxf(vz + bb.z, 0.f);
            float ow = fmaxf(vw + bb.w, 0.f);
            __half hx, lx, hy, ly, hz, lz, hw, lw;
            split_h(ox, hx, lx);
            split_h(oy, hy, ly);
            split_h(oz, hz, lz);
            split_h(ow, hw, lw);
            size_t idx = (size_t)(b * HW + yy * IMGW + xx) * C + co;
            uint2 ph = make_uint2(pack_h2(hx, hy), pack_h2(hz, hw));
            uint2 pl = make_uint2(pack_h2(lx, ly), pack_h2(lz, lw));
            *reinterpret_cast<uint2*>(&g_yh[idx]) = ph;
            *reinterpret_cast<uint2*>(&g_yl[idx]) = pl;
        }
    }
}

// ---------------- fp16-split GEMM; compute-first mbarrier pipeline ---------------
__global__ void __launch_bounds__(256, 2) gemm_hmma(
    const __half* __restrict__ Ah, const __half* __restrict__ Al,
    const __half* __restrict__ Bh, const __half* __restrict__ Bl,
    const float* __restrict__ bias,
    __half* __restrict__ Oh, __half* __restrict__ Ol, float* __restrict__ Of,
    int relu_split, size_t zsA, size_t zsB, size_t zsO)
{
    extern __shared__ __align__(128) char smem[];
    const uint32_t sb  = smem_u32(smem);
    const uint32_t bar = sb + BAR_OFF;   // full[s]=bar+s*16, empty[s]=bar+s*16+8
    const int tid = threadIdx.x;
    const int m0  = blockIdx.y * BM;
    const int n0  = blockIdx.x * BN;
    const size_t zA = (size_t)blockIdx.z * zsA;
    const size_t zB = (size_t)blockIdx.z * zsB;
    const size_t zO = (size_t)blockIdx.z * zsO;
    Ah += zA; Al += zA; Bh += zB; Bl += zB;

    if (tid == 0) {
        #pragma unroll
        for (int s = 0; s < 3; ++s) {
            MBAR_INIT(bar + s * 16,     256);
            MBAR_INIT(bar + s * 16 + 8, 256);
        }
    }
    __syncthreads();

    const int arow  = tid >> 1;
    const int ahalf = tid & 1;
    const __half* aptr = (ahalf ? Al : Ah) + (size_t)(m0 + arow) * C;
    const uint32_t a_swz  = (arow >> 1) & 3;
    const uint32_t a_soff = (ahalf ? SA_L : SA_H) + arow * 64;

    auto load_chunk = [&](int c) {
        const uint32_t sdata = sb + (uint32_t)(c % 3) * STG;
        const int ci0 = c * 32;
        #pragma unroll
        for (int c16 = 0; c16 < 4; ++c16) {
            int sz = (ci0 + c16 * 8 < C) ? 16 : 0;
            cp16(sdata + a_soff + (((uint32_t)c16 ^ a_swz) << 4), aptr + ci0 + c16 * 8, sz);
        }
        #pragma unroll
        for (int i = 0; i < 5; ++i) {
            int lin = i * 256 + tid;
            if (lin < 1152) {
                int row = lin >> 3, sub = lin & 7;
                int hb = sub >> 2, c16 = sub & 3;
                int sz = (ci0 + c16 * 8 < C) ? 16 : 0;
                const __half* bp = hb ? Bl : Bh;
                const __half* bsrc = bp + (size_t)(n0 + row) * C + ci0 + c16 * 8;
                uint32_t off = (hb ? SB_L : SB_H) + row * 64
                             + (((uint32_t)(c16 ^ ((row >> 1) & 3))) << 4);
                cp16(sdata + off, bsrc, sz);
            }
        }
        CP_ASYNC_MBAR_ARRIVE(bar + (uint32_t)(c % 3) * 16);
    };

    const int warp = tid >> 5, lane = tid & 31;
    const int wm = warp >> 1, wn = warp & 1;
    const int g  = lane >> 3;
    const int a_rf   = (g & 1) * 8 + (lane & 7);
    const int a_c16b = g >> 1;
    const int b_rf8  = lane & 7;
    const int b_k16  = (lane >> 3) & 1;
    const int b_g2   = (lane >> 4) & 1;
    const int laneB  = lane & 15;
    const int b_rf   = laneB & 7;
    const int b_c16b = laneB >> 3;

    float acc[2][9][4];
    #pragma unroll
    for (int mi = 0; mi < 2; ++mi)
        #pragma unroll
        for (int nj = 0; nj < 9; ++nj)
            #pragma unroll
            for (int q = 0; q < 4; ++q) acc[mi][nj][q] = 0.f;

    load_chunk(0);
    load_chunk(1);
    load_chunk(2);

    for (int c = 0; c < CPT; ++c) {
        MBAR_WAIT(bar + (uint32_t)(c % 3) * 16, (c / 3) & 1);

        const uint32_t sd = sb + (uint32_t)(c % 3) * STG;

        uint32_t aH[2][4], aL[2][4];
        uint32_t bh[2][4], bl[2][4];
        uint32_t rh0, rh1, rl0, rl1;

        auto ldA = [&](int ks) {
            #pragma unroll
            for (int mi = 0; mi < 2; ++mi) {
                int r = wm * 32 + mi * 16 + a_rf;
                uint32_t c16l = (uint32_t)(ks * 2 + a_c16b);
                uint32_t addr = sd + r * 64 + ((c16l ^ ((r >> 1) & 3)) << 4);
                ldsm4(aH[mi], addr + SA_H);
                ldsm4(aL[mi], addr + SA_L);
            }
        };
        auto ldB4 = [&](int ks, int njp, int buf) {
            int r = wn * 72 + (njp * 2 + b_g2) * 8 + b_rf8;
            uint32_t c16l = (uint32_t)(ks * 2 + b_k16);
            uint32_t addr = sd + r * 64 + ((c16l ^ ((r >> 1) & 3)) << 4);
            ldsm4(bh[buf], addr + SB_H);
            ldsm4(bl[buf], addr + SB_L);
        };
        auto ldB2 = [&](int ks) {
            int r = wn * 72 + 8 * 8 + b_rf;
            uint32_t c16l = (uint32_t)(ks * 2 + b_c16b);
            uint32_t addr = sd + r * 64 + ((c16l ^ ((r >> 1) & 3)) << 4);
            ldsm2(rh0, rh1, addr + SB_H);
            ldsm2(rl0, rl1, addr + SB_L);
        };
        auto mm12 = [&](int njp, int buf) {
            const int j0 = njp * 2, j1 = njp * 2 + 1;
            uint32_t* h = bh[buf];
            uint32_t* l = bl[buf];
            mma16816(acc[0][j0], aH[0], h[0], h[1]);
            mma16816(acc[1][j0], aH[1], h[0], h[1]);
            mma16816(acc[0][j1], aH[0], h[2], h[3]);
            mma16816(acc[1][j1], aH[1], h[2], h[3]);
            mma16816(acc[0][j0], aH[0], l[0], l[1]);
            mma16816(acc[1][j0], aH[1], l[0], l[1]);
            mma16816(acc[0][j1], aH[0], l[2], l[3]);
            mma16816(acc[1][j1], aH[1], l[2], l[3]);
            mma16816(acc[0][j0], aL[0], h[0], h[1]);
            mma16816(acc[1][j0], aL[1], h[0], h[1]);
            mma16816(acc[0][j1], aL[0], h[2], h[3]);
            mma16816(acc[1][j1], aL[1], h[2], h[3]);
        };
        auto mm6 = [&]() {
            mma16816(acc[0][8], aH[0], rh0, rh1);
            mma16816(acc[1][8], aH[1], rh0, rh1);
            mma16816(acc[0][8], aH[0], rl0, rl1);
            mma16816(acc[1][8], aH[1], rl0, rl1);
            mma16816(acc[0][8], aL[0], rh0, rh1);
            mma16816(acc[1][8], aL[1], rh0, rh1);
        };

        // ---- ks = 0 ----
        ldA(0);
        ldB4(0, 0, 0);
        #pragma unroll
        for (int njp = 0; njp < 4; ++njp) {
            const int cur = njp & 1, nxt = cur ^ 1;
            if (njp < 3) {
                ldB4(0, njp + 1, nxt);
            } else {
                ldB2(0);
                ldB4(1, 0, nxt);
            }
            mm12(njp, cur);
        }
        mm6();
        // ---- ks = 1 ----
        ldA(1);
        #pragma unroll
        for (int njp = 0; njp < 4; ++njp) {
            const int cur = njp & 1, nxt = cur ^ 1;
            if (njp < 3) ldB4(1, njp + 1, nxt);
            else         ldB2(1);
            mm12(njp, cur);
        }
        mm6();

        MBAR_ARRIVE(bar + (uint32_t)(c % 3) * 16 + 8);

        const int nc = c + 3;
        if (nc < CPT) {
            MBAR_WAIT(bar + (uint32_t)(nc % 3) * 16 + 8, ((nc / 3) - 1) & 1);
            load_chunk(nc);
        }
    }

    // epilogue
    const int qrow = lane >> 2;
    const int qcol = (lane & 3) * 2;
    #pragma unroll
    for (int nj = 0; nj < 9; ++nj) {
        const int ncol = n0 + wn * 72 + nj * 8 + qcol;
        const float b0 = __ldg(bias + ncol);
        const float b1 = __ldg(bias + ncol + 1);
        #pragma unroll
        for (int mi = 0; mi < 2; ++mi) {
            const int mr = m0 + wm * 32 + mi * 16 + qrow;
            float v00 = acc[mi][nj][0] + b0;
            float v01 = acc[mi][nj][1] + b1;
            float v10 = acc[mi][nj][2] + b0;
            float v11 = acc[mi][nj][3] + b1;
            if (relu_split) {
                v00 = fmaxf(v00, 0.f); v01 = fmaxf(v01, 0.f);
                v10 = fmaxf(v10, 0.f); v11 = fmaxf(v11, 0.f);
                __half h0, l0, h1, l1;
                split_h(v00, h0, l0); split_h(v01, h1, l1);
                *reinterpret_cast<__half2*>(Oh + (size_t)mr * C + ncol) = __halves2half2(h0, h1);
                *reinterpret_cast<__half2*>(Ol + (size_t)mr * C + ncol) = __halves2half2(l0, l1);
                split_h(v10, h0, l0); split_h(v11, h1, l1);
                *reinterpret_cast<__half2*>(Oh + (size_t)(mr + 8) * C + ncol) = __halves2half2(h0, h1);
                *reinterpret_cast<__half2*>(Ol + (size_t)(mr + 8) * C + ncol) = __halves2half2(l0, l1);
            } else {
                float* ofp = Of + zO;
                *reinterpret_cast<float2*>(ofp + (size_t)mr * C + ncol)       = make_float2(v00, v01);
                *reinterpret_cast<float2*>(ofp + (size_t)(mr + 8) * C + ncol) = make_float2(v10, v11);
            }
        }
    }
}

// ---------------- finalize: protos staged in dynamic smem ------------------------
__global__ __launch_bounds__(256) void finalize(
    const float* __restrict__ p,
    const float* __restrict__ lng, const float* __restrict__ lnb,
    const float* __restrict__ lmg, const float* __restrict__ lmb,
    float* __restrict__ out)
{
    extern __shared__ float sprot[];          // 20*C floats
    for (int j = threadIdx.x; j < 20 * C; j += 256)
        sprot[j] = g_protN[j];
    __syncthreads();

    int gw   = (blockIdx.x * 256 + threadIdx.x) >> 5;
    int lane = threadIdx.x & 31;
    if (gw >= NPIX) return;
    const float* row = p + (size_t)gw * C;

    float x[23];
    float s = 0.f, ss = 0.f;
    #pragma unroll
    for (int i = 0; i < 23; ++i) {
        int j = lane + i * 32;
        float v = (j < C) ? row[j] : 0.f;
        x[i] = v; s += v; ss += v * v;
    }
    #pragma unroll
    for (int o = 16; o; o >>= 1) {
        s  += __shfl_xor_sync(0xffffffffu, s,  o);
        ss += __shfl_xor_sync(0xffffffffu, ss, o);
    }
    float mu   = s * (1.f / C);
    float var  = ss * (1.f / C) - mu * mu;
    float rstd = rsqrtf(var + 1e-5f);

    float nsq = 0.f;
    #pragma unroll
    for (int i = 0; i < 23; ++i) {
        int j = lane + i * 32;
        float v = 0.f;
        if (j < C) v = (x[i] - mu) * rstd * lng[j] + lnb[j];
        x[i] = v;
        nsq += v * v;
    }
    #pragma unroll
    for (int o = 16; o; o >>= 1) nsq += __shfl_xor_sync(0xffffffffu, nsq, o);
    float inv = 1.f / fmaxf(sqrtf(nsq), 1e-12f);

    float sc[2];
    #pragma unroll
    for (int k = 0; k < 2; ++k) {
        float best = -3.4e38f;
        for (int m = 0; m < 10; ++m) {
            const float* pr = sprot + (k * 10 + m) * C;
            float d = 0.f;
            #pragma unroll
            for (int i = 0; i < 23; ++i) {
                int j = lane + i * 32;
                if (j < C) d += x[i] * pr[j];
            }
            #pragma unroll
            for (int o = 16; o; o >>= 1) d += __shfl_xor_sync(0xffffffffu, d, o);
            best = fmaxf(best, d * inv);
        }
        sc[k] = best;
    }

    float mu2 = 0.5f * (sc[0] + sc[1]);
    float d0 = sc[0] - mu2, d1 = sc[1] - mu2;
    float va = 0.5f * (d0 * d0 + d1 * d1);
    float r2 = rsqrtf(va + 1e-5f);
    if (lane < 2) {
        int b = gw / HW, rem = gw - b * HW;
        out[(b * 2 + lane) * HW + rem] = (sc[lane] - mu2) * r2 * lmg[lane] + lmb[lane];
    }
}

// ---------------- launch ----------------------------------------------------------
extern "C" void kernel_launch(void* const* d_in, const int* in_sizes, int n_in,
                              void* d_out, int out_size)
{
    const float* feat1      = (const float*)d_in[0];
    const float* feat2      = (const float*)d_in[1];
    const float* feat3      = (const float*)d_in[2];
    const float* feat4      = (const float*)d_in[3];
    const float* cls_w      = (const float*)d_in[4];
    const float* cls_b      = (const float*)d_in[5];
    const float* cls_bn_g   = (const float*)d_in[6];
    const float* cls_bn_b   = (const float*)d_in[7];
    const float* cls_bn_rm  = (const float*)d_in[8];
    const float* cls_bn_rv  = (const float*)d_in[9];
    const float* proj_w1    = (const float*)d_in[10];
    const float* proj_b1    = (const float*)d_in[11];
    const float* proj_bn_g  = (const float*)d_in[12];
    const float* proj_bn_b  = (const float*)d_in[13];
    const float* proj_bn_rm = (const float*)d_in[14];
    const float* proj_bn_rv = (const float*)d_in[15];
    const float* proj_w2    = (const float*)d_in[16];
    const float* proj_b2    = (const float*)d_in[17];
    const float* ln_feat_g  = (const float*)d_in[18];
    const float* ln_feat_b  = (const float*)d_in[19];
    const float* ln_mask_g  = (const float*)d_in[20];
    const float* ln_mask_b  = (const float*)d_in[21];
    const float* prototypes = (const float*)d_in[22];
    float* out = (float*)d_out;

    float *feats, *gm, *gout, *b3, *b1a, *b1b, *bz;
    __half *vh, *vl, *uh, *ul, *yh, *yl, *xh, *xl, *w1ah, *w1al, *w1bh, *w1bl;
    cudaGetSymbolAddress((void**)&feats, g_feats);
    cudaGetSymbolAddress((void**)&vh,    g_vh);
    cudaGetSymbolAddress((void**)&vl,    g_vl);
    cudaGetSymbolAddress((void**)&gm,    g_m);
    cudaGetSymbolAddress((void**)&uh,    g_uh);
    cudaGetSymbolAddress((void**)&ul,    g_ul);
    cudaGetSymbolAddress((void**)&yh,    g_yh);
    cudaGetSymbolAddress((void**)&yl,    g_yl);
    cudaGetSymbolAddress((void**)&xh,    g_xh);
    cudaGetSymbolAddress((void**)&xl,    g_xl);
    cudaGetSymbolAddress((void**)&gout,  g_out);
    cudaGetSymbolAddress((void**)&w1ah,  g_w1ah);
    cudaGetSymbolAddress((void**)&w1al,  g_w1al);
    cudaGetSymbolAddress((void**)&w1bh,  g_w1bh);
    cudaGetSymbolAddress((void**)&w1bl,  g_w1bl);
    cudaGetSymbolAddress((void**)&b3,    g_b3);
    cudaGetSymbolAddress((void**)&b1a,   g_b1a);
    cudaGetSymbolAddress((void**)&b1b,   g_b1b);
    cudaGetSymbolAddress((void**)&bz,    g_zero);

    cudaFuncSetAttribute(gemm_hmma, cudaFuncAttributeMaxDynamicSharedMemorySize, SMEM_BYTES);
    cudaFuncSetAttribute(finalize,  cudaFuncAttributeMaxDynamicSharedMemorySize, PROT_SMEM);

    // Fused preps: one launch covers wU + wt1 + bias + protos (independent work).
    prep_all<<<2 * NWU + 3 + 20, 256>>>(cls_w, cls_bn_g, cls_bn_rv,
                                        proj_w1, proj_w2, proj_bn_g, proj_bn_rv,
                                        cls_b, cls_bn_b, cls_bn_rm,
                                        proj_b1, proj_bn_b, proj_bn_rm, proj_b2,
                                        prototypes);                               // 0
    {
        dim3 bfGrid(NPIX / 32, 30);
        dim3 bfBlock(32, 8);
        build_feats<<<bfGrid, bfBlock>>>(feat1, feat2, feat3, feat4);              // 1
    }
    wino_in<<<NT4, 360>>>(feats);                                                  // 2

    // 36 winograd GEMMs: [1152,720] x [720,720] -> fp32 M
    dim3 gridW(C / BN, NT4 / BM, 36);                                              // 3
    gemm_hmma<<<gridW, 256, SMEM_BYTES>>>(vh, vl, uh, ul, bz,
                                          nullptr, nullptr, gm, 0,
                                          (size_t)NT4 * C, (size_t)C * C,
                                          (size_t)NT4 * C);

    wino_out<<<NT4, 192>>>(gm, b3);                                                // 4

    dim3 grid1(C / BN, NPIX / BM, 1);
    gemm_hmma<<<grid1, 256, SMEM_BYTES>>>(yh, yl, w1ah, w1al, b1a,
                                          xh, xl, nullptr, 1, 0, 0, 0);            // 5
    gemm_hmma<<<grid1, 256, SMEM_BYTES>>>(xh, xl, w1bh, w1bl, b1b,
                                          nullptr, nullptr, gout, 0, 0, 0, 0);     // 6

    finalize<<<(NPIX * 32 + 255) / 256, 256, PROT_SMEM>>>(gout, ln_feat_g, ln_feat_b,
                                                          ln_mask_g, ln_mask_b, out); // 7
}

// round 17
// speedup vs baseline: 1.0315x; 1.0231x over previous
#include <cuda_runtime.h>
#include <cuda_fp16.h>
#include <cstdint>
#include <math.h>

#define C      720
#define HW     9216
#define NPIX   18432
#define IMGW   96
#define NT4    1152              // 2 batch * 24*24 winograd F(4,3) tiles
#define BM     128
#define BN     144
#define CPT    23                // ceil(720/32) k-chunks of 32

// smem stage layout (bytes)
#define SA_H 0
#define SA_L 8192
#define SB_H 16384
#define SB_L 25600
#define STG  34816
#define BAR_OFF (3 * STG)               // 104448: 3x(full,empty) mbarriers
#define SMEM_BYTES (BAR_OFF + 64)       // 104512 -> 2 CTAs/SM

#define NWU (C * C / 2 / 256 + 1)       // 1013 blocks for wU / wt1 halves
#define PROT_SMEM (20 * C * 4)          // 57600 bytes

// ---------------- scratch -------------------------------------------------------
__device__ float  g_feats[NPIX*C];
__device__ __half g_vh[36*NT4*C], g_vl[36*NT4*C];   // F(4,3) input transform
__device__ float  g_m [36*NT4*C];                   // winograd GEMM output
__device__ __half g_uh[36*C*C], g_ul[36*C*C];       // F(4,3) weights [e][co][ci]
__device__ __half g_yh[NPIX*C], g_yl[NPIX*C];
__device__ __half g_xh[NPIX*C], g_xl[NPIX*C];
__device__ float  g_out[NPIX*C];
__device__ __half g_w1ah[C*C], g_w1al[C*C];
__device__ __half g_w1bh[C*C], g_w1bl[C*C];
__device__ float  g_b3[C], g_b1a[C], g_b1b[C];
__device__ float  g_zero[C];
__device__ float  g_protN[20*C];

// ---------------- helpers -------------------------------------------------------
__device__ __forceinline__ uint32_t smem_u32(const void* p) {
    uint32_t a;
    asm("{ .reg .u64 t; cvta.to.shared.u64 t, %1; cvt.u32.u64 %0, t; }" : "=r"(a) : "l"(p));
    return a;
}

__device__ __forceinline__ void split_h(float v, __half& hi, __half& lo) {
    hi = __float2half_rn(v);
    lo = __float2half_rn(v - __half2float(hi));
}

__device__ __forceinline__ void cp16(uint32_t dst, const void* src, int sz) {
    asm volatile("cp.async.cg.shared.global [%0], [%1], 16, %2;"
                 :: "r"(dst), "l"(src), "r"(sz));
}

__device__ __forceinline__ void ldsm4(uint32_t* r, uint32_t addr) {
    asm volatile("ldmatrix.sync.aligned.m8n8.x4.shared.b16 {%0,%1,%2,%3}, [%4];"
                 : "=r"(r[0]), "=r"(r[1]), "=r"(r[2]), "=r"(r[3]) : "r"(addr));
}

__device__ __forceinline__ void ldsm2(uint32_t& r0, uint32_t& r1, uint32_t addr) {
    asm volatile("ldmatrix.sync.aligned.m8n8.x2.shared.b16 {%0,%1}, [%2];"
                 : "=r"(r0), "=r"(r1) : "r"(addr));
}

__device__ __forceinline__ void mma16816(float* c, const uint32_t* a,
                                         uint32_t b0, uint32_t b1) {
    asm volatile(
        "mma.sync.aligned.m16n8k16.row.col.f32.f16.f16.f32 "
        "{%0,%1,%2,%3}, {%4,%5,%6,%7}, {%8,%9}, {%0,%1,%2,%3};"
        : "+f"(c[0]), "+f"(c[1]), "+f"(c[2]), "+f"(c[3])
        : "r"(a[0]), "r"(a[1]), "r"(a[2]), "r"(a[3]), "r"(b0), "r"(b1));
}

// mbarrier primitives (sm_80/sm_90 baseline)
#define MBAR_INIT(a, cnt) \
    asm volatile("mbarrier.init.shared.b64 [%0], %1;" :: "r"(a), "r"(cnt) : "memory")
#define MBAR_ARRIVE(a) do { \
    uint64_t _st; \
    asm volatile("mbarrier.arrive.shared.b64 %0, [%1];" : "=l"(_st) : "r"(a) : "memory"); \
} while (0)
// .noinc is load-bearing: default variant pre-increments expected count -> deadlock.
#define CP_ASYNC_MBAR_ARRIVE(a) \
    asm volatile("cp.async.mbarrier.arrive.noinc.shared.b64 [%0];" :: "r"(a) : "memory")
#define MBAR_WAIT(a, ph) do { \
    uint32_t _m = (a); uint32_t _p = (uint32_t)(ph); \
    asm volatile("{\n\t.reg .pred P1;\n\t" \
        "WL_%=:\n\t" \
        "mbarrier.try_wait.parity.shared.b64 P1, [%0], %1;\n\t" \
        "@P1 bra.uni WD_%=;\n\t" \
        "bra.uni WL_%=;\n\t" \
        "WD_%=:\n\t}" :: "r"(_m), "r"(_p) : "memory"); \
} while (0)

// B^T row apply (F(4,3)): identical expression order to the scalar version
__device__ __forceinline__ float btrow(int i, float a0, float a1, float a2,
                                       float a3, float a4, float a5) {
    switch (i) {
    case 0:  return 4.f*a0 - 5.f*a2 + a4;
    case 1:  return -4.f*a1 - 4.f*a2 + a3 + a4;
    case 2:  return  4.f*a1 - 4.f*a2 - a3 + a4;
    case 3:  return -2.f*a1 - a2 + 2.f*a3 + a4;
    case 4:  return  2.f*a1 - a2 - 2.f*a3 + a4;
    default: return  4.f*a1 - 5.f*a3 + a5;
    }
}
// A^T row apply (F(4,3) output)
__device__ __forceinline__ float atrow(int i, float a0, float a1, float a2,
                                       float a3, float a4, float a5) {
    switch (i) {
    case 0:  return a0 + a1 + a2 + a3 + a4;
    case 1:  return a1 - a2 + 2.f*a3 - 2.f*a4;
    case 2:  return a1 + a2 + 4.f*a3 + 4.f*a4;
    default: return a1 - a2 + 8.f*a3 - 8.f*a4 + a5;
    }
}

__device__ __forceinline__ uint32_t pack_h2(__half a, __half b) {
    __half2 h = __halves2half2(a, b);
    return *reinterpret_cast<uint32_t*>(&h);
}

// ---------------- fused prep kernel ----------------------------------------------
__global__ void __launch_bounds__(256) prep_all(
    const float* __restrict__ w,   const float* __restrict__ cbg,
    const float* __restrict__ crv,
    const float* __restrict__ w1,  const float* __restrict__ w2,
    const float* __restrict__ pbg, const float* __restrict__ prv,
    const float* __restrict__ cb,  const float* __restrict__ cbb,
    const float* __restrict__ crm,
    const float* __restrict__ pb1, const float* __restrict__ pbb,
    const float* __restrict__ prm, const float* __restrict__ pb2,
    const float* __restrict__ proto)
{
    const int bid = blockIdx.x;

    if (bid < NWU) {
        int o2 = bid * 256 + threadIdx.x;
        if (o2 >= C * C / 2) return;
        int o  = o2 * 2;
        int co = o / C;
        int ci = o - co * C;
        float inv = cbg[co] * rsqrtf(crv[co] + 1e-5f);

        float2 g[3][3];
        #pragma unroll
        for (int r = 0; r < 3; ++r)
            #pragma unroll
            for (int c = 0; c < 3; ++c) {
                g[r][c].x = w[((size_t)(co * C + ci)) * 9 + r * 3 + c] * inv;
                g[r][c].y = w[((size_t)(co * C + ci + 1)) * 9 + r * 3 + c] * inv;
            }

        float2 q[6][3];
        #pragma unroll
        for (int c = 0; c < 3; ++c) {
            q[0][c].x = 0.25f * g[0][c].x;                       q[0][c].y = 0.25f * g[0][c].y;
            q[1][c].x = (-1.f/6.f) * (g[0][c].x + g[1][c].x + g[2][c].x);
            q[1][c].y = (-1.f/6.f) * (g[0][c].y + g[1][c].y + g[2][c].y);
            q[2][c].x = (-1.f/6.f) * (g[0][c].x - g[1][c].x + g[2][c].x);
            q[2][c].y = (-1.f/6.f) * (g[0][c].y - g[1][c].y + g[2][c].y);
            q[3][c].x = (1.f/24.f) * g[0][c].x + (1.f/12.f) * g[1][c].x + (1.f/6.f) * g[2][c].x;
            q[3][c].y = (1.f/24.f) * g[0][c].y + (1.f/12.f) * g[1][c].y + (1.f/6.f) * g[2][c].y;
            q[4][c].x = (1.f/24.f) * g[0][c].x - (1.f/12.f) * g[1][c].x + (1.f/6.f) * g[2][c].x;
            q[4][c].y = (1.f/24.f) * g[0][c].y - (1.f/12.f) * g[1][c].y + (1.f/6.f) * g[2][c].y;
            q[5][c] = g[2][c];
        }
        #pragma unroll
        for (int i = 0; i < 6; ++i) {
            float usx[6], usy[6];
            usx[0] = 0.25f * q[i][0].x;                          usy[0] = 0.25f * q[i][0].y;
            usx[1] = (-1.f/6.f) * (q[i][0].x + q[i][1].x + q[i][2].x);
            usy[1] = (-1.f/6.f) * (q[i][0].y + q[i][1].y + q[i][2].y);
            usx[2] = (-1.f/6.f) * (q[i][0].x - q[i][1].x + q[i][2].x);
            usy[2] = (-1.f/6.f) * (q[i][0].y - q[i][1].y + q[i][2].y);
            usx[3] = (1.f/24.f) * q[i][0].x + (1.f/12.f) * q[i][1].x + (1.f/6.f) * q[i][2].x;
            usy[3] = (1.f/24.f) * q[i][0].y + (1.f/12.f) * q[i][1].y + (1.f/6.f) * q[i][2].y;
            usx[4] = (1.f/24.f) * q[i][0].x - (1.f/12.f) * q[i][1].x + (1.f/6.f) * q[i][2].x;
            usy[4] = (1.f/24.f) * q[i][0].y - (1.f/12.f) * q[i][1].y + (1.f/6.f) * q[i][2].y;
            usx[5] = q[i][2].x;                                  usy[5] = q[i][2].y;
            #pragma unroll
            for (int j = 0; j < 6; ++j) {
                int e = i * 6 + j;
                __half hx, lx, hy, ly;
                split_h(usx[j], hx, lx);
                split_h(usy[j], hy, ly);
                size_t idx = (size_t)e * C * C + o;
                *reinterpret_cast<uint32_t*>(&g_uh[idx]) = pack_h2(hx, hy);
                *reinterpret_cast<uint32_t*>(&g_ul[idx]) = pack_h2(lx, ly);
            }
        }
    } else if (bid < 2 * NWU) {
        int o2 = (bid - NWU) * 256 + threadIdx.x;
        if (o2 >= C * C / 2) return;
        int o  = o2 * 2;
        int co = o / C;
        float inv = pbg[co] * rsqrtf(prv[co] + 1e-5f);
        float2 a = *reinterpret_cast<const float2*>(w1 + o);
        float2 b = *reinterpret_cast<const float2*>(w2 + o);
        __half hx, lx, hy, ly;
        split_h(a.x * inv, hx, lx); split_h(a.y * inv, hy, ly);
        *reinterpret_cast<uint32_t*>(&g_w1ah[o]) = pack_h2(hx, hy);
        *reinterpret_cast<uint32_t*>(&g_w1al[o]) = pack_h2(lx, ly);
        split_h(b.x, hx, lx); split_h(b.y, hy, ly);
        *reinterpret_cast<uint32_t*>(&g_w1bh[o]) = pack_h2(hx, hy);
        *reinterpret_cast<uint32_t*>(&g_w1bl[o]) = pack_h2(lx, ly);
    } else if (bid < 2 * NWU + 3) {
        int co = (bid - 2 * NWU) * 256 + threadIdx.x;
        if (co >= C) return;
        float inv3 = cbg[co] * rsqrtf(crv[co] + 1e-5f);
        g_b3[co]  = (cb[co]  - crm[co]) * inv3 + cbb[co];
        float inv1 = pbg[co] * rsqrtf(prv[co] + 1e-5f);
        g_b1a[co] = (pb1[co] - prm[co]) * inv1 + pbb[co];
        g_b1b[co] = pb2[co];
    } else {
        __shared__ float red[8];
        int p = bid - (2 * NWU + 3);
        const float* src = proto + p * C;
        float ss = 0.f;
        for (int j = threadIdx.x; j < C; j += 256) { float v = src[j]; ss += v * v; }
        #pragma unroll
        for (int o = 16; o; o >>= 1) ss += __shfl_xor_sync(0xffffffffu, ss, o);
        if ((threadIdx.x & 31) == 0) red[threadIdx.x >> 5] = ss;
        __syncthreads();
        if (threadIdx.x == 0) {
            float t = 0.f;
            #pragma unroll
            for (int i = 0; i < 8; ++i) t += red[i];
            red[0] = 1.f / fmaxf(sqrtf(t), 1e-12f);
        }
        __syncthreads();
        float inv = red[0];
        for (int j = threadIdx.x; j < C; j += 256)
            g_protN[p * C + j] = src[j] * inv;
    }
}

// ---------------- build feats: coalesced tiled-transpose --------------------------
__device__ __forceinline__ void ac_coord(int o, int S, int& i0, int& i1, float& w)
{
    float f = (float)o * (float)(S - 1) / 95.f;
    i0 = (int)floorf(f);
    i1 = min(i0 + 1, S - 1);
    w  = f - (float)i0;
}

__global__ void __launch_bounds__(256) build_feats(
    const float* __restrict__ f1, const float* __restrict__ f2,
    const float* __restrict__ f3, const float* __restrict__ f4)
{
    __shared__ float sm[24][33];
    const int tx = threadIdx.x;
    const int ty = threadIdx.y;
    const int p0 = blockIdx.x * 32;
    const int c0 = blockIdx.y * 24;
    const int pix = p0 + tx;
    const int b   = pix / HW;
    const int rem = pix - b * HW;
    const int y   = rem / IMGW;
    const int x   = rem - y * IMGW;

    if (c0 < 48) {
        #pragma unroll
        for (int kk = 0; kk < 3; ++kk) {
            int c = c0 + ty + kk * 8;
            sm[ty + kk * 8][tx] = f1[((size_t)(b * 48 + c) * IMGW + y) * IMGW + x];
        }
    } else if (c0 < 144) {
        int y0, y1, x0, x1; float wy, wx;
        ac_coord(y, 48, y0, y1, wy);
        ac_coord(x, 48, x0, x1, wx);
        #pragma unroll
        for (int kk = 0; kk < 3; ++kk) {
            int c = c0 + ty + kk * 8;
            const float* p = f2 + (size_t)(b * 96 + (c - 48)) * 48 * 48;
            float v00 = p[y0 * 48 + x0], v01 = p[y0 * 48 + x1];
            float v10 = p[y1 * 48 + x0], v11 = p[y1 * 48 + x1];
            sm[ty + kk * 8][tx] = (v00 * (1.f - wy) + v10 * wy) * (1.f - wx)
                                + (v01 * (1.f - wy) + v11 * wy) * wx;
        }
    } else if (c0 < 336) {
        int y0, y1, x0, x1; float wy, wx;
        ac_coord(y, 24, y0, y1, wy);
        ac_coord(x, 24, x0, x1, wx);
        #pragma unroll
        for (int kk = 0; kk < 3; ++kk) {
            int c = c0 + ty + kk * 8;
            const float* p = f3 + (size_t)(b * 192 + (c - 144)) * 24 * 24;
            float v00 = p[y0 * 24 + x0], v01 = p[y0 * 24 + x1];
            float v10 = p[y1 * 24 + x0], v11 = p[y1 * 24 + x1];
            sm[ty + kk * 8][tx] = (v00 * (1.f - wy) + v10 * wy) * (1.f - wx)
                                + (v01 * (1.f - wy) + v11 * wy) * wx;
        }
    } else {
        int y0, y1, x0, x1; float wy, wx;
        ac_coord(y, 12, y0, y1, wy);
        ac_coord(x, 12, x0, x1, wx);
        #pragma unroll
        for (int kk = 0; kk < 3; ++kk) {
            int c = c0 + ty + kk * 8;
            const float* p = f4 + (size_t)(b * 384 + (c - 336)) * 12 * 12;
            float v00 = p[y0 * 12 + x0], v01 = p[y0 * 12 + x1];
            float v10 = p[y1 * 12 + x0], v11 = p[y1 * 12 + x1];
            sm[ty + kk * 8][tx] = (v00 * (1.f - wy) + v10 * wy) * (1.f - wx)
                                + (v01 * (1.f - wy) + v11 * wy) * wx;
        }
    }
    __syncthreads();

    const int tid = ty * 32 + tx;
    #pragma unroll
    for (int i = tid; i < 32 * 24; i += 256) {
        int pp = i / 24;
        int cc = i - pp * 24;
        g_feats[(size_t)(p0 + pp) * C + c0 + cc] = sm[cc][pp];
    }
}

// ---------------- F(4,3) input transform, 2 channels/thread ----------------------
__global__ void __launch_bounds__(384) wino_in(const float* __restrict__ feats)
{
    int tile = blockIdx.x;
    int ci   = threadIdx.x * 2;     // 0..718, blockDim 360
    if (ci >= C) return;
    int b  = tile / 576;
    int r  = tile - b * 576;
    int ty = r / 24, tx = r - ty * 24;
    int y0 = ty * 4 - 1, x0 = tx * 4 - 1;

    float2 d[6][6];
    #pragma unroll
    for (int i = 0; i < 6; ++i) {
        int y = y0 + i;
        #pragma unroll
        for (int j = 0; j < 6; ++j) {
            int x = x0 + j;
            bool ok = (y >= 0) & (y < IMGW) & (x >= 0) & (x < IMGW);
            d[i][j] = ok ? *reinterpret_cast<const float2*>(
                                &feats[(size_t)(b * HW + y * IMGW + x) * C + ci])
                         : make_float2(0.f, 0.f);
        }
    }
    #pragma unroll
    for (int i = 0; i < 6; ++i) {
        float2 t[6];
        #pragma unroll
        for (int c = 0; c < 6; ++c) {
            t[c].x = btrow(i, d[0][c].x, d[1][c].x, d[2][c].x, d[3][c].x, d[4][c].x, d[5][c].x);
            t[c].y = btrow(i, d[0][c].y, d[1][c].y, d[2][c].y, d[3][c].y, d[4][c].y, d[5][c].y);
        }
        #pragma unroll
        for (int j = 0; j < 6; ++j) {
            float vx = btrow(j, t[0].x, t[1].x, t[2].x, t[3].x, t[4].x, t[5].x);
            float vy = btrow(j, t[0].y, t[1].y, t[2].y, t[3].y, t[4].y, t[5].y);
            int e = i * 6 + j;
            __half hx, lx, hy, ly;
            split_h(vx, hx, lx);
            split_h(vy, hy, ly);
            size_t idx = ((size_t)e * NT4 + tile) * C + ci;
            *reinterpret_cast<uint32_t*>(&g_vh[idx]) = pack_h2(hx, hy);
            *reinterpret_cast<uint32_t*>(&g_vl[idx]) = pack_h2(lx, ly);
        }
    }
}

// ---------------- F(4,3) output transform, 4 channels/thread ---------------------
__global__ void __launch_bounds__(192) wino_out(const float* __restrict__ M,
                                                const float* __restrict__ bias)
{
    int tile = blockIdx.x;
    int co   = threadIdx.x * 4;     // 0..716, blockDim 180 used of 192
    if (co >= C) return;
    float4 m[6][6];
    #pragma unroll
    for (int e = 0; e < 36; ++e)
        m[e / 6][e % 6] = *reinterpret_cast<const float4*>(
                               &M[((size_t)e * NT4 + tile) * C + co]);

    float4 bb = *reinterpret_cast<const float4*>(bias + co);
    int b  = tile / 576;
    int r  = tile - b * 576;
    int ty = r / 24, tx = r - ty * 24;
    int py = ty * 4, px = tx * 4;

    #pragma unroll
    for (int i = 0; i < 4; ++i) {
        float4 s[6];
        #pragma unroll
        for (int c = 0; c < 6; ++c) {
            s[c].x = atrow(i, m[0][c].x, m[1][c].x, m[2][c].x, m[3][c].x, m[4][c].x, m[5][c].x);
            s[c].y = atrow(i, m[0][c].y, m[1][c].y, m[2][c].y, m[3][c].y, m[4][c].y, m[5][c].y);
            s[c].z = atrow(i, m[0][c].z, m[1][c].z, m[2][c].z, m[3][c].z, m[4][c].z, m[5][c].z);
            s[c].w = atrow(i, m[0][c].w, m[1][c].w, m[2][c].w, m[3][c].w, m[4][c].w, m[5][c].w);
        }
        #pragma unroll
        for (int j = 0; j < 4; ++j) {
            float vx = atrow(j, s[0].x, s[1].x, s[2].x, s[3].x, s[4].x, s[5].x);
            float vy = atrow(j, s[0].y, s[1].y, s[2].y, s[3].y, s[4].y, s[5].y);
            float vz = atrow(j, s[0].z, s[1].z, s[2].z, s[3].z, s[4].z, s[5].z);
            float vw = atrow(j, s[0].w, s[1].w, s[2].w, s[3].w, s[4].w, s[5].w);
            int yy = py + i, xx = px + j;
            float ox = fmaxf(vx + bb.x, 0.f);
            float oy = fmaxf(vy + bb.y, 0.f);
            float oz = fmaxf(vz + bb.z, 0.f);
            float ow = fmaxf(vw + bb.w, 0.f);
            __half hx, lx, hy, ly, hz, lz, hw, lw;
            split_h(ox, hx, lx);
            split_h(oy, hy, ly);
            split_h(oz, hz, lz);
            split_h(ow, hw, lw);
            size_t idx = (size_t)(b * HW + yy * IMGW + xx) * C + co;
            uint2 ph = make_uint2(pack_h2(hx, hy), pack_h2(hz, hw));
            uint2 pl = make_uint2(pack_h2(lx, ly), pack_h2(lz, lw));
            *reinterpret_cast<uint2*>(&g_yh[idx]) = ph;
            *reinterpret_cast<uint2*>(&g_yl[idx]) = pl;
        }
    }
}

// ---------------- fp16-split GEMM; compute-first mbarrier pipeline ---------------
__global__ void __launch_bounds__(256, 2) gemm_hmma(
    const __half* __restrict__ Ah, const __half* __restrict__ Al,
    const __half* __restrict__ Bh, const __half* __restrict__ Bl,
    const float* __restrict__ bias,
    __half* __restrict__ Oh, __half* __restrict__ Ol, float* __restrict__ Of,
    int relu_split, size_t zsA, size_t zsB, size_t zsO)
{
    extern __shared__ __align__(128) char smem[];
    const uint32_t sb  = smem_u32(smem);
    const uint32_t bar = sb + BAR_OFF;   // full[s]=bar+s*16, empty[s]=bar+s*16+8
    const int tid = threadIdx.x;
    const int m0  = blockIdx.y * BM;
    const int n0  = blockIdx.x * BN;
    const size_t zA = (size_t)blockIdx.z * zsA;
    const size_t zB = (size_t)blockIdx.z * zsB;
    const size_t zO = (size_t)blockIdx.z * zsO;
    Ah += zA; Al += zA; Bh += zB; Bl += zB;

    if (tid == 0) {
        #pragma unroll
        for (int s = 0; s < 3; ++s) {
            MBAR_INIT(bar + s * 16,     256);
            MBAR_INIT(bar + s * 16 + 8, 256);
        }
    }
    __syncthreads();

    const int arow  = tid >> 1;
    const int ahalf = tid & 1;
    const __half* aptr = (ahalf ? Al : Ah) + (size_t)(m0 + arow) * C;
    const uint32_t a_swz  = (arow >> 1) & 3;
    const uint32_t a_soff = (ahalf ? SA_L : SA_H) + arow * 64;

    auto load_chunk = [&](int c) {
        const uint32_t sdata = sb + (uint32_t)(c % 3) * STG;
        const int ci0 = c * 32;
        #pragma unroll
        for (int c16 = 0; c16 < 4; ++c16) {
            int sz = (ci0 + c16 * 8 < C) ? 16 : 0;
            cp16(sdata + a_soff + (((uint32_t)c16 ^ a_swz) << 4), aptr + ci0 + c16 * 8, sz);
        }
        #pragma unroll
        for (int i = 0; i < 5; ++i) {
            int lin = i * 256 + tid;
            if (lin < 1152) {
                int row = lin >> 3, sub = lin & 7;
                int hb = sub >> 2, c16 = sub & 3;
                int sz = (ci0 + c16 * 8 < C) ? 16 : 0;
                const __half* bp = hb ? Bl : Bh;
                const __half* bsrc = bp + (size_t)(n0 + row) * C + ci0 + c16 * 8;
                uint32_t off = (hb ? SB_L : SB_H) + row * 64
                             + (((uint32_t)(c16 ^ ((row >> 1) & 3))) << 4);
                cp16(sdata + off, bsrc, sz);
            }
        }
        CP_ASYNC_MBAR_ARRIVE(bar + (uint32_t)(c % 3) * 16);
    };

    const int warp = tid >> 5, lane = tid & 31;
    const int wm = warp >> 1, wn = warp & 1;
    const int g  = lane >> 3;
    const int a_rf   = (g & 1) * 8 + (lane & 7);
    const int a_c16b = g >> 1;
    const int b_rf8  = lane & 7;
    const int b_k16  = (lane >> 3) & 1;
    const int b_g2   = (lane >> 4) & 1;
    const int laneB  = lane & 15;
    const int b_rf   = laneB & 7;
    const int b_c16b = laneB >> 3;

    float acc[2][9][4];
    #pragma unroll
    for (int mi = 0; mi < 2; ++mi)
        #pragma unroll
        for (int nj = 0; nj < 9; ++nj)
            #pragma unroll
            for (int q = 0; q < 4; ++q) acc[mi][nj][q] = 0.f;

    load_chunk(0);
    load_chunk(1);
    load_chunk(2);

    for (int c = 0; c < CPT; ++c) {
        MBAR_WAIT(bar + (uint32_t)(c % 3) * 16, (c / 3) & 1);

        const uint32_t sd = sb + (uint32_t)(c % 3) * STG;

        uint32_t aH[2][4], aL[2][4];
        uint32_t bh[2][4], bl[2][4];
        uint32_t rh0, rh1, rl0, rl1;

        auto ldA = [&](int ks) {
            #pragma unroll
            for (int mi = 0; mi < 2; ++mi) {
                int r = wm * 32 + mi * 16 + a_rf;
                uint32_t c16l = (uint32_t)(ks * 2 + a_c16b);
                uint32_t addr = sd + r * 64 + ((c16l ^ ((r >> 1) & 3)) << 4);
                ldsm4(aH[mi], addr + SA_H);
                ldsm4(aL[mi], addr + SA_L);
            }
        };
        auto ldB4 = [&](int ks, int njp, int buf) {
            int r = wn * 72 + (njp * 2 + b_g2) * 8 + b_rf8;
            uint32_t c16l = (uint32_t)(ks * 2 + b_k16);
            uint32_t addr = sd + r * 64 + ((c16l ^ ((r >> 1) & 3)) << 4);
            ldsm4(bh[buf], addr + SB_H);
            ldsm4(bl[buf], addr + SB_L);
        };
        auto ldB2 = [&](int ks) {
            int r = wn * 72 + 8 * 8 + b_rf;
            uint32_t c16l = (uint32_t)(ks * 2 + b_c16b);
            uint32_t addr = sd + r * 64 + ((c16l ^ ((r >> 1) & 3)) << 4);
            ldsm2(rh0, rh1, addr + SB_H);
            ldsm2(rl0, rl1, addr + SB_L);
        };
        auto mm12 = [&](int njp, int buf) {
            const int j0 = njp * 2, j1 = njp * 2 + 1;
            uint32_t* h = bh[buf];
            uint32_t* l = bl[buf];
            mma16816(acc[0][j0], aH[0], h[0], h[1]);
            mma16816(acc[1][j0], aH[1], h[0], h[1]);
            mma16816(acc[0][j1], aH[0], h[2], h[3]);
            mma16816(acc[1][j1], aH[1], h[2], h[3]);
            mma16816(acc[0][j0], aH[0], l[0], l[1]);
            mma16816(acc[1][j0], aH[1], l[0], l[1]);
            mma16816(acc[0][j1], aH[0], l[2], l[3]);
            mma16816(acc[1][j1], aH[1], l[2], l[3]);
            mma16816(acc[0][j0], aL[0], h[0], h[1]);
            mma16816(acc[1][j0], aL[1], h[0], h[1]);
            mma16816(acc[0][j1], aL[0], h[2], h[3]);
            mma16816(acc[1][j1], aL[1], h[2], h[3]);
        };
        auto mm6 = [&]() {
            mma16816(acc[0][8], aH[0], rh0, rh1);
            mma16816(acc[1][8], aH[1], rh0, rh1);
            mma16816(acc[0][8], aH[0], rl0, rl1);
            mma16816(acc[1][8], aH[1], rl0, rl1);
            mma16816(acc[0][8], aL[0], rh0, rh1);
            mma16816(acc[1][8], aL[1], rh0, rh1);
        };

        // ---- ks = 0 ----
        ldA(0);
        ldB4(0, 0, 0);
        #pragma unroll
        for (int njp = 0; njp < 4; ++njp) {
            const int cur = njp & 1, nxt = cur ^ 1;
            if (njp < 3) {
                ldB4(0, njp + 1, nxt);
            } else {
                ldB2(0);
                ldB4(1, 0, nxt);
            }
            mm12(njp, cur);
        }
        mm6();
        // ---- ks = 1 ----
        ldA(1);
        #pragma unroll
        for (int njp = 0; njp < 4; ++njp) {
            const int cur = njp & 1, nxt = cur ^ 1;
            if (njp < 3) ldB4(1, njp + 1, nxt);
            else         ldB2(1);
            mm12(njp, cur);
        }
        mm6();

        MBAR_ARRIVE(bar + (uint32_t)(c % 3) * 16 + 8);

        const int nc = c + 3;
        if (nc < CPT) {
            MBAR_WAIT(bar + (uint32_t)(nc % 3) * 16 + 8, ((nc / 3) - 1) & 1);
            load_chunk(nc);
        }
    }

    // epilogue
    const int qrow = lane >> 2;
    const int qcol = (lane & 3) * 2;
    #pragma unroll
    for (int nj = 0; nj < 9; ++nj) {
        const int ncol = n0 + wn * 72 + nj * 8 + qcol;
        const float b0 = __ldg(bias + ncol);
        const float b1 = __ldg(bias + ncol + 1);
        #pragma unroll
        for (int mi = 0; mi < 2; ++mi) {
            const int mr = m0 + wm * 32 + mi * 16 + qrow;
            float v00 = acc[mi][nj][0] + b0;
            float v01 = acc[mi][nj][1] + b1;
            float v10 = acc[mi][nj][2] + b0;
            float v11 = acc[mi][nj][3] + b1;
            if (relu_split) {
                v00 = fmaxf(v00, 0.f); v01 = fmaxf(v01, 0.f);
                v10 = fmaxf(v10, 0.f); v11 = fmaxf(v11, 0.f);
                __half h0, l0, h1, l1;
                split_h(v00, h0, l0); split_h(v01, h1, l1);
                *reinterpret_cast<__half2*>(Oh + (size_t)mr * C + ncol) = __halves2half2(h0, h1);
                *reinterpret_cast<__half2*>(Ol + (size_t)mr * C + ncol) = __halves2half2(l0, l1);
                split_h(v10, h0, l0); split_h(v11, h1, l1);
                *reinterpret_cast<__half2*>(Oh + (size_t)(mr + 8) * C + ncol) = __halves2half2(h0, h1);
                *reinterpret_cast<__half2*>(Ol + (size_t)(mr + 8) * C + ncol) = __halves2half2(l0, l1);
            } else {
                float* ofp = Of + zO;
                *reinterpret_cast<float2*>(ofp + (size_t)mr * C + ncol)       = make_float2(v00, v01);
                *reinterpret_cast<float2*>(ofp + (size_t)(mr + 8) * C + ncol) = make_float2(v10, v11);
            }
        }
    }
}

// ---------------- finalize: 1024 thr/block, protos staged in smem ----------------
__global__ __launch_bounds__(1024) void finalize(
    const float* __restrict__ p,
    const float* __restrict__ lng, const float* __restrict__ lnb,
    const float* __restrict__ lmg, const float* __restrict__ lmb,
    float* __restrict__ out)
{
    extern __shared__ float sprot[];          // 20*C floats
    for (int j = threadIdx.x; j < 20 * C; j += 1024)
        sprot[j] = g_protN[j];
    __syncthreads();

    int gw   = (blockIdx.x * 1024 + threadIdx.x) >> 5;
    int lane = threadIdx.x & 31;
    if (gw >= NPIX) return;
    const float* row = p + (size_t)gw * C;

    float x[23];
    float s = 0.f, ss = 0.f;
    #pragma unroll
    for (int i = 0; i < 23; ++i) {
        int j = lane + i * 32;
        float v = (j < C) ? row[j] : 0.f;
        x[i] = v; s += v; ss += v * v;
    }
    #pragma unroll
    for (int o = 16; o; o >>= 1) {
        s  += __shfl_xor_sync(0xffffffffu, s,  o);
        ss += __shfl_xor_sync(0xffffffffu, ss, o);
    }
    float mu   = s * (1.f / C);
    float var  = ss * (1.f / C) - mu * mu;
    float rstd = rsqrtf(var + 1e-5f);

    float nsq = 0.f;
    #pragma unroll
    for (int i = 0; i < 23; ++i) {
        int j = lane + i * 32;
        float v = 0.f;
        if (j < C) v = (x[i] - mu) * rstd * lng[j] + lnb[j];
        x[i] = v;
        nsq += v * v;
    }
    #pragma unroll
    for (int o = 16; o; o >>= 1) nsq += __shfl_xor_sync(0xffffffffu, nsq, o);
    float inv = 1.f / fmaxf(sqrtf(nsq), 1e-12f);

    float sc[2];
    #pragma unroll
    for (int k = 0; k < 2; ++k) {
        float best = -3.4e38f;
        for (int m = 0; m < 10; ++m) {
            const float* pr = sprot + (k * 10 + m) * C;
            float d = 0.f;
            #pragma unroll
            for (int i = 0; i < 23; ++i) {
                int j = lane + i * 32;
                if (j < C) d += x[i] * pr[j];
            }
            #pragma unroll
            for (int o = 16; o; o >>= 1) d += __shfl_xor_sync(0xffffffffu, d, o);
            best = fmaxf(best, d * inv);
        }
        sc[k] = best;
    }

    float mu2 = 0.5f * (sc[0] + sc[1]);
    float d0 = sc[0] - mu2, d1 = sc[1] - mu2;
    float va = 0.5f * (d0 * d0 + d1 * d1);
    float r2 = rsqrtf(va + 1e-5f);
    if (lane < 2) {
        int b = gw / HW, rem = gw - b * HW;
        out[(b * 2 + lane) * HW + rem] = (sc[lane] - mu2) * r2 * lmg[lane] + lmb[lane];
    }
}

// ---------------- launch ----------------------------------------------------------
extern "C" void kernel_launch(void* const* d_in, const int* in_sizes, int n_in,
                              void* d_out, int out_size)
{
    const float* feat1      = (const float*)d_in[0];
    const float* feat2      = (const float*)d_in[1];
    const float* feat3      = (const float*)d_in[2];
    const float* feat4      = (const float*)d_in[3];
    const float* cls_w      = (const float*)d_in[4];
    const float* cls_b      = (const float*)d_in[5];
    const float* cls_bn_g   = (const float*)d_in[6];
    const float* cls_bn_b   = (const float*)d_in[7];
    const float* cls_bn_rm  = (const float*)d_in[8];
    const float* cls_bn_rv  = (const float*)d_in[9];
    const float* proj_w1    = (const float*)d_in[10];
    const float* proj_b1    = (const float*)d_in[11];
    const float* proj_bn_g  = (const float*)d_in[12];
    const float* proj_bn_b  = (const float*)d_in[13];
    const float* proj_bn_rm = (const float*)d_in[14];
    const float* proj_bn_rv = (const float*)d_in[15];
    const float* proj_w2    = (const float*)d_in[16];
    const float* proj_b2    = (const float*)d_in[17];
    const float* ln_feat_g  = (const float*)d_in[18];
    const float* ln_feat_b  = (const float*)d_in[19];
    const float* ln_mask_g  = (const float*)d_in[20];
    const float* ln_mask_b  = (const float*)d_in[21];
    const float* prototypes = (const float*)d_in[22];
    float* out = (float*)d_out;

    float *feats, *gm, *gout, *b3, *b1a, *b1b, *bz;
    __half *vh, *vl, *uh, *ul, *yh, *yl, *xh, *xl, *w1ah, *w1al, *w1bh, *w1bl;
    cudaGetSymbolAddress((void**)&feats, g_feats);
    cudaGetSymbolAddress((void**)&vh,    g_vh);
    cudaGetSymbolAddress((void**)&vl,    g_vl);
    cudaGetSymbolAddress((void**)&gm,    g_m);
    cudaGetSymbolAddress((void**)&uh,    g_uh);
    cudaGetSymbolAddress((void**)&ul,    g_ul);
    cudaGetSymbolAddress((void**)&yh,    g_yh);
    cudaGetSymbolAddress((void**)&yl,    g_yl);
    cudaGetSymbolAddress((void**)&xh,    g_xh);
    cudaGetSymbolAddress((void**)&xl,    g_xl);
    cudaGetSymbolAddress((void**)&gout,  g_out);
    cudaGetSymbolAddress((void**)&w1ah,  g_w1ah);
    cudaGetSymbolAddress((void**)&w1al,  g_w1al);
    cudaGetSymbolAddress((void**)&w1bh,  g_w1bh);
    cudaGetSymbolAddress((void**)&w1bl,  g_w1bl);
    cudaGetSymbolAddress((void**)&b3,    g_b3);
    cudaGetSymbolAddress((void**)&b1a,   g_b1a);
    cudaGetSymbolAddress((void**)&b1b,   g_b1b);
    cudaGetSymbolAddress((void**)&bz,    g_zero);

    cudaFuncSetAttribute(gemm_hmma, cudaFuncAttributeMaxDynamicSharedMemorySize, SMEM_BYTES);
    cudaFuncSetAttribute(finalize,  cudaFuncAttributeMaxDynamicSharedMemorySize, PROT_SMEM);

    // Fused preps: one launch covers wU + wt1 + bias + protos (independent work).
    prep_all<<<2 * NWU + 3 + 20, 256>>>(cls_w, cls_bn_g, cls_bn_rv,
                                        proj_w1, proj_w2, proj_bn_g, proj_bn_rv,
                                        cls_b, cls_bn_b, cls_bn_rm,
                                        proj_b1, proj_bn_b, proj_bn_rm, proj_b2,
                                        prototypes);                               // 0
    {
        dim3 bfGrid(NPIX / 32, 30);
        dim3 bfBlock(32, 8);
        build_feats<<<bfGrid, bfBlock>>>(feat1, feat2, feat3, feat4);              // 1
    }
    wino_in<<<NT4, 360>>>(feats);                                                  // 2

    // 36 winograd GEMMs: [1152,720] x [720,720] -> fp32 M
    dim3 gridW(C / BN, NT4 / BM, 36);                                              // 3
    gemm_hmma<<<gridW, 256, SMEM_BYTES>>>(vh, vl, uh, ul, bz,
                                          nullptr, nullptr, gm, 0,
                                          (size_t)NT4 * C, (size_t)C * C,
                                          (size_t)NT4 * C);

    wino_out<<<NT4, 192>>>(gm, b3);                                                // 4

    dim3 grid1(C / BN, NPIX / BM, 1);
    gemm_hmma<<<grid1, 256, SMEM_BYTES>>>(yh, yl, w1ah, w1al, b1a,
                                          xh, xl, nullptr, 1, 0, 0, 0);            // 5
    gemm_hmma<<<grid1, 256, SMEM_BYTES>>>(xh, xl, w1bh, w1bl, b1b,
                                          nullptr, nullptr, gout, 0, 0, 0, 0);     // 6

    finalize<<<(NPIX * 32 + 1023) / 1024, 1024, PROT_SMEM>>>(gout, ln_feat_g, ln_feat_b,
                                                             ln_mask_g, ln_mask_b, out); // 7
}